// round 1
// baseline (speedup 1.0000x reference)
#include <cuda_runtime.h>
#include <math.h>

// Problem constants
#define B_   8
#define C_   512
#define N_   4096
#define G_   8
#define CPG  64            // C_/G_
#define O3   1536          // 3*C_
#define EPSV 1e-6f
#define QSCALE 0.04419417382415922f   // 512^-0.5

// ---------------------------------------------------------------------------
// Scratch (static device globals; no runtime allocation allowed)
// ---------------------------------------------------------------------------
__device__ float g_qkv[(size_t)B_ * O3 * N_];   // 192 MB: q|k|v slabs per batch
__device__ float g_Wb [(size_t)B_ * O3 * C_];   // 25 MB: GN-folded qkv weights per batch
__device__ float g_biasb[B_ * O3];              // folded qkv bias per batch
__device__ float g_mean[B_ * G_];
__device__ float g_rstd[B_ * G_];
__device__ float g_ctx[(size_t)B_ * C_ * C_];   // 8 MB: context = k_sm @ v^T
__device__ float g_M  [(size_t)B_ * C_ * C_];   // 8 MB: proj_w @ ctx^T

// ---------------------------------------------------------------------------
// Reductions
// ---------------------------------------------------------------------------
__device__ __forceinline__ float warp_sum(float v) {
#pragma unroll
    for (int o = 16; o > 0; o >>= 1) v += __shfl_xor_sync(0xffffffffu, v, o);
    return v;
}
__device__ __forceinline__ float warp_max(float v) {
#pragma unroll
    for (int o = 16; o > 0; o >>= 1) v = fmaxf(v, __shfl_xor_sync(0xffffffffu, v, o));
    return v;
}
__device__ __forceinline__ float block_sum(float v, float* sh) {
    int tid = threadIdx.x, nw = blockDim.x >> 5;
    __syncthreads();
    v = warp_sum(v);
    if ((tid & 31) == 0) sh[tid >> 5] = v;
    __syncthreads();
    if (tid < 32) {
        float w = (tid < nw) ? sh[tid] : 0.f;
        w = warp_sum(w);
        if (tid == 0) sh[0] = w;
    }
    __syncthreads();
    return sh[0];
}
__device__ __forceinline__ float block_max(float v, float* sh) {
    int tid = threadIdx.x, nw = blockDim.x >> 5;
    __syncthreads();
    v = warp_max(v);
    if ((tid & 31) == 0) sh[tid >> 5] = v;
    __syncthreads();
    if (tid < 32) {
        float w = (tid < nw) ? sh[tid] : -3.402823466e38f;
        w = warp_max(w);
        if (tid == 0) sh[0] = w;
    }
    __syncthreads();
    return sh[0];
}

// ---------------------------------------------------------------------------
// Kernel 1: GroupNorm statistics (per batch,group mean & rstd)
// grid = B*G blocks; each reduces CPG*N contiguous floats
// ---------------------------------------------------------------------------
__global__ __launch_bounds__(256) void gn_stats_kernel(const float* __restrict__ x) {
    int bg = blockIdx.x;                       // 0..63  (b*G + g); group data is contiguous
    const float4* xv = (const float4*)(x + (size_t)bg * CPG * N_);
    const int total = CPG * N_ / 4;            // 65536 float4
    float s = 0.f, ss = 0.f;
    for (int i = threadIdx.x; i < total; i += 256) {
        float4 v = xv[i];
        s += v.x + v.y + v.z + v.w;
        ss = fmaf(v.x, v.x, fmaf(v.y, v.y, fmaf(v.z, v.z, fmaf(v.w, v.w, ss))));
    }
    __shared__ float sh[32];
    s  = block_sum(s, sh);
    ss = block_sum(ss, sh);
    if (threadIdx.x == 0) {
        const float inv = 1.f / (float)(CPG * N_);
        float m = s * inv;
        float var = ss * inv - m * m;
        g_mean[bg] = m;
        g_rstd[bg] = rsqrtf(var + EPSV);
    }
}

// ---------------------------------------------------------------------------
// Kernel 2: Fold GroupNorm (+ q scale) into qkv weights & bias, per batch.
//   h = a*x + d with a[b,c]=rstd*scale[c], d[b,c]=bias[c]-mean*a
//   Wb[b,o,c] = qs * W[o,c]*a[b,c];  biasb[b,o] = qs*(qkv_b[o] + sum_c W[o,c]*d[b,c])
// grid = B*O3 blocks of 128 threads (one output row each)
// ---------------------------------------------------------------------------
__global__ __launch_bounds__(128) void prep_w_kernel(
    const float* __restrict__ qkv_w, const float* __restrict__ qkv_b,
    const float* __restrict__ gn_scale, const float* __restrict__ gn_bias) {
    int bo = blockIdx.x;
    int b = bo / O3, o = bo % O3;
    float qs = (o < C_) ? QSCALE : 1.f;        // fold q * C^-0.5 into weights/bias
    const float* wrow = qkv_w + (size_t)o * C_;
    float* wb = g_Wb + (size_t)bo * C_;
    float acc = 0.f;
    for (int c = threadIdx.x; c < C_; c += 128) {
        int g = c >> 6;                        // c / CPG
        float rstd = g_rstd[b * G_ + g];
        float mean = g_mean[b * G_ + g];
        float a = rstd * gn_scale[c];
        float d = gn_bias[c] - mean * a;
        float w = wrow[c];
        wb[c] = w * a * qs;
        acc = fmaf(w, d, acc);
    }
    __shared__ float sh[32];
    acc = block_sum(acc, sh);
    if (threadIdx.x == 0) g_biasb[bo] = qs * (qkv_b[o] + acc);
}

// ---------------------------------------------------------------------------
// Kernel 3/7: batched NN SGEMM  C[m,n] = sum_k A[m,k]*B[k,n] (+bias[m]) (+resid)
// 128x128 tile, BK=8, 8x8 per thread, 256 threads. All dims divisible.
// ---------------------------------------------------------------------------
__global__ __launch_bounds__(256) void gemm_nn(
    const float* __restrict__ A, size_t sA, int lda,
    const float* __restrict__ Bm, size_t sB, int ldb,
    float* __restrict__ Cm, size_t sC, int ldc,
    const float* __restrict__ bias, int sBias,
    const float* __restrict__ resid, size_t sR,
    int M, int Nn, int K) {
    const int bz = blockIdx.z;
    const float* Ab = A  + (size_t)bz * sA;
    const float* Bb = Bm + (size_t)bz * sB;
    float*       Cb = Cm + (size_t)bz * sC;
    const int m0 = blockIdx.y * 128;
    const int n0 = blockIdx.x * 128;

    __shared__ float As[8][128];
    __shared__ float Bs[8][128];

    const int tid = threadIdx.x;
    const int tx = tid & 15, ty = tid >> 4;    // 16x16 thread grid
    const int arow = tid >> 1, acol4 = (tid & 1) * 4;
    const int brow = tid >> 5, bcol4 = (tid & 31) * 4;

    float acc[8][8] = {};

    for (int k0 = 0; k0 < K; k0 += 8) {
        float4 av = *(const float4*)(Ab + (size_t)(m0 + arow) * lda + k0 + acol4);
        As[acol4 + 0][arow] = av.x;
        As[acol4 + 1][arow] = av.y;
        As[acol4 + 2][arow] = av.z;
        As[acol4 + 3][arow] = av.w;
        *(float4*)&Bs[brow][bcol4] =
            *(const float4*)(Bb + (size_t)(k0 + brow) * ldb + n0 + bcol4);
        __syncthreads();
#pragma unroll
        for (int k = 0; k < 8; k++) {
            float a[8], b[8];
            *(float4*)&a[0] = *(const float4*)&As[k][ty * 8];
            *(float4*)&a[4] = *(const float4*)&As[k][ty * 8 + 4];
            *(float4*)&b[0] = *(const float4*)&Bs[k][tx * 8];
            *(float4*)&b[4] = *(const float4*)&Bs[k][tx * 8 + 4];
#pragma unroll
            for (int i = 0; i < 8; i++)
#pragma unroll
                for (int j = 0; j < 8; j++)
                    acc[i][j] = fmaf(a[i], b[j], acc[i][j]);
        }
        __syncthreads();
    }

#pragma unroll
    for (int i = 0; i < 8; i++) {
        int m = m0 + ty * 8 + i;
        float bval = bias ? bias[bz * sBias + m] : 0.f;
#pragma unroll
        for (int j = 0; j < 8; j += 4) {
            int n = n0 + tx * 8 + j;
            float4 r;
            r.x = acc[i][j + 0] + bval;
            r.y = acc[i][j + 1] + bval;
            r.z = acc[i][j + 2] + bval;
            r.w = acc[i][j + 3] + bval;
            if (resid) {
                float4 rv = *(const float4*)(resid + (size_t)bz * sR + (size_t)m * ldc + n);
                r.x += rv.x; r.y += rv.y; r.z += rv.z; r.w += rv.w;
            }
            *(float4*)(Cb + (size_t)m * ldc + n) = r;
        }
    }
}

// ---------------------------------------------------------------------------
// Kernel 4: in-place softmax over tokens for the k slab rows
// grid = B*C blocks; one 4096-float row each, held in registers
// ---------------------------------------------------------------------------
__global__ __launch_bounds__(256) void softmax_k_kernel() {
    int row = blockIdx.x;                      // 0..B*C-1
    int b = row / C_, d = row % C_;
    float4* p = (float4*)(g_qkv + ((size_t)b * O3 + C_ + d) * N_);
    const int tid = threadIdx.x;
    float4 v[4];
    float mx = -3.402823466e38f;
#pragma unroll
    for (int i = 0; i < 4; i++) {
        v[i] = p[tid + i * 256];
        mx = fmaxf(mx, fmaxf(fmaxf(v[i].x, v[i].y), fmaxf(v[i].z, v[i].w)));
    }
    __shared__ float sh[32];
    mx = block_max(mx, sh);
    float s = 0.f;
#pragma unroll
    for (int i = 0; i < 4; i++) {
        v[i].x = __expf(v[i].x - mx);
        v[i].y = __expf(v[i].y - mx);
        v[i].z = __expf(v[i].z - mx);
        v[i].w = __expf(v[i].w - mx);
        s += v[i].x + v[i].y + v[i].z + v[i].w;
    }
    s = block_sum(s, sh);
    float inv = 1.f / s;
#pragma unroll
    for (int i = 0; i < 4; i++) {
        v[i].x *= inv; v[i].y *= inv; v[i].z *= inv; v[i].w *= inv;
        p[tid + i * 256] = v[i];
    }
}

// ---------------------------------------------------------------------------
// Kernel 5/6: batched NT SGEMM  C[m,n] = sum_k A[m,k]*B[n,k]
// 64x64 tile, BK=16, 4x4 per thread, 256 threads. All dims divisible.
// ---------------------------------------------------------------------------
__global__ __launch_bounds__(256) void gemm_nt(
    const float* __restrict__ A, size_t sA, int lda,
    const float* __restrict__ Bm, size_t sB, int ldb,
    float* __restrict__ Cm, size_t sC, int ldc,
    int M, int Nn, int K) {
    const int bz = blockIdx.z;
    const float* Ab = A  + (size_t)bz * sA;
    const float* Bb = Bm + (size_t)bz * sB;
    float*       Cb = Cm + (size_t)bz * sC;
    const int m0 = blockIdx.y * 64;
    const int n0 = blockIdx.x * 64;

    __shared__ float As[16][64];
    __shared__ float Bs[16][64];

    const int tid = threadIdx.x;
    const int tx = tid & 15, ty = tid >> 4;
    const int lrow = tid >> 2, lkq = (tid & 3) * 4;  // 64 rows x 4 k-quads

    float acc[4][4] = {};

    for (int k0 = 0; k0 < K; k0 += 16) {
        float4 av = *(const float4*)(Ab + (size_t)(m0 + lrow) * lda + k0 + lkq);
        As[lkq + 0][lrow] = av.x;
        As[lkq + 1][lrow] = av.y;
        As[lkq + 2][lrow] = av.z;
        As[lkq + 3][lrow] = av.w;
        float4 bv = *(const float4*)(Bb + (size_t)(n0 + lrow) * ldb + k0 + lkq);
        Bs[lkq + 0][lrow] = bv.x;
        Bs[lkq + 1][lrow] = bv.y;
        Bs[lkq + 2][lrow] = bv.z;
        Bs[lkq + 3][lrow] = bv.w;
        __syncthreads();
#pragma unroll
        for (int k = 0; k < 16; k++) {
            float4 a = *(const float4*)&As[k][ty * 4];
            float4 b = *(const float4*)&Bs[k][tx * 4];
            acc[0][0] = fmaf(a.x, b.x, acc[0][0]); acc[0][1] = fmaf(a.x, b.y, acc[0][1]);
            acc[0][2] = fmaf(a.x, b.z, acc[0][2]); acc[0][3] = fmaf(a.x, b.w, acc[0][3]);
            acc[1][0] = fmaf(a.y, b.x, acc[1][0]); acc[1][1] = fmaf(a.y, b.y, acc[1][1]);
            acc[1][2] = fmaf(a.y, b.z, acc[1][2]); acc[1][3] = fmaf(a.y, b.w, acc[1][3]);
            acc[2][0] = fmaf(a.z, b.x, acc[2][0]); acc[2][1] = fmaf(a.z, b.y, acc[2][1]);
            acc[2][2] = fmaf(a.z, b.z, acc[2][2]); acc[2][3] = fmaf(a.z, b.w, acc[2][3]);
            acc[3][0] = fmaf(a.w, b.x, acc[3][0]); acc[3][1] = fmaf(a.w, b.y, acc[3][1]);
            acc[3][2] = fmaf(a.w, b.z, acc[3][2]); acc[3][3] = fmaf(a.w, b.w, acc[3][3]);
        }
        __syncthreads();
    }

#pragma unroll
    for (int i = 0; i < 4; i++) {
        int m = m0 + ty * 4 + i;
        float4 r;
        r.x = acc[i][0]; r.y = acc[i][1]; r.z = acc[i][2]; r.w = acc[i][3];
        *(float4*)(Cb + (size_t)m * ldc + n0 + tx * 4) = r;
    }
}

// ---------------------------------------------------------------------------
// Launch sequence
// ---------------------------------------------------------------------------
extern "C" void kernel_launch(void* const* d_in, const int* in_sizes, int n_in,
                              void* d_out, int out_size) {
    const float* x        = (const float*)d_in[0];
    const float* qkv_w    = (const float*)d_in[1];
    const float* qkv_b    = (const float*)d_in[2];
    const float* proj_w   = (const float*)d_in[3];
    const float* proj_b   = (const float*)d_in[4];
    const float* gn_scale = (const float*)d_in[5];
    const float* gn_bias  = (const float*)d_in[6];
    float* out = (float*)d_out;

    float *qkv, *Wb, *biasb, *ctx, *Mm;
    cudaGetSymbolAddress((void**)&qkv,   g_qkv);
    cudaGetSymbolAddress((void**)&Wb,    g_Wb);
    cudaGetSymbolAddress((void**)&biasb, g_biasb);
    cudaGetSymbolAddress((void**)&ctx,   g_ctx);
    cudaGetSymbolAddress((void**)&Mm,    g_M);

    // 1) GroupNorm stats
    gn_stats_kernel<<<B_ * G_, 256>>>(x);
    // 2) Fold GN + q-scale into qkv weights (per batch)
    prep_w_kernel<<<B_ * O3, 128>>>(qkv_w, qkv_b, gn_scale, gn_bias);
    // 3) qkv = Wb @ x + biasb          [1536,512]@[512,4096] per batch
    gemm_nn<<<dim3(N_ / 128, O3 / 128, B_), 256>>>(
        Wb,  (size_t)O3 * C_, C_,
        x,   (size_t)C_ * N_, N_,
        qkv, (size_t)O3 * N_, N_,
        biasb, O3,
        nullptr, 0,
        O3, N_, C_);
    // 4) softmax over tokens on k slab (in place)
    softmax_k_kernel<<<B_ * C_, 256>>>();
    // 5) ctx[d,e] = sum_n k_sm[d,n] v[e,n]      [512,512] per batch
    gemm_nt<<<dim3(C_ / 64, C_ / 64, B_), 256>>>(
        qkv + (size_t)C_ * N_,     (size_t)O3 * N_, N_,
        qkv + (size_t)2 * C_ * N_, (size_t)O3 * N_, N_,
        ctx, (size_t)C_ * C_, C_,
        C_, C_, N_);
    // 6) M[o,d] = sum_e proj_w[o,e] ctx[d,e]    (fold projection through context)
    gemm_nt<<<dim3(C_ / 64, C_ / 64, B_), 256>>>(
        proj_w, 0,                  C_,
        ctx,    (size_t)C_ * C_,    C_,
        Mm,     (size_t)C_ * C_,    C_,
        C_, C_, C_);
    // 7) out = M @ q + proj_b + x               [512,512]@[512,4096] per batch
    gemm_nn<<<dim3(N_ / 128, C_ / 128, B_), 256>>>(
        Mm,  (size_t)C_ * C_, C_,
        qkv, (size_t)O3 * N_, N_,
        out, (size_t)C_ * N_, N_,
        proj_b, 0,
        x, (size_t)C_ * N_,
        C_, N_, C_);
}

// round 3
// speedup vs baseline: 2.1749x; 2.1749x over previous
#include <cuda_runtime.h>
#include <cuda_bf16.h>
#include <cstdint>
#include <math.h>

// Problem constants
#define B_   8
#define C_   512
#define N_   4096
#define G_   8
#define CPG  64
#define O3   1536
#define EPSV 1e-6f
#define QSCALE 0.04419417382415922f   // 512^-0.5

// ---------------------------------------------------------------------------
// PTX helpers (base ISA only: ldmatrix / mma.sync / cp.async -- no tcgen05)
// ---------------------------------------------------------------------------
__device__ __forceinline__ uint32_t smem_u32(const void* p) {
    uint32_t a;
    asm("{ .reg .u64 t; cvta.to.shared.u64 t, %1; cvt.u32.u64 %0, t; }" : "=r"(a) : "l"(p));
    return a;
}
__device__ __forceinline__ void ldsm_x4(uint32_t (&r)[4], uint32_t addr) {
    asm volatile("ldmatrix.sync.aligned.m8n8.x4.shared.b16 {%0,%1,%2,%3}, [%4];"
        : "=r"(r[0]), "=r"(r[1]), "=r"(r[2]), "=r"(r[3]) : "r"(addr));
}
__device__ __forceinline__ void ldsm_x2(uint32_t (&r)[2], uint32_t addr) {
    asm volatile("ldmatrix.sync.aligned.m8n8.x2.shared.b16 {%0,%1}, [%2];"
        : "=r"(r[0]), "=r"(r[1]) : "r"(addr));
}
__device__ __forceinline__ void mma16816(float (&d)[4], const uint32_t (&a)[4],
                                         const uint32_t (&b)[2]) {
    asm volatile(
        "mma.sync.aligned.m16n8k16.row.col.f32.bf16.bf16.f32 "
        "{%0,%1,%2,%3}, {%4,%5,%6,%7}, {%8,%9}, {%0,%1,%2,%3};"
        : "+f"(d[0]), "+f"(d[1]), "+f"(d[2]), "+f"(d[3])
        : "r"(a[0]), "r"(a[1]), "r"(a[2]), "r"(a[3]), "r"(b[0]), "r"(b[1]));
}
#define CP_ASYNC16(dst, src) \
    asm volatile("cp.async.cg.shared.global [%0], [%1], 16;" :: "r"(dst), "l"(src))
#define CP_COMMIT() asm volatile("cp.async.commit_group;" ::: "memory")
#define CP_WAIT0()  asm volatile("cp.async.wait_group 0;" ::: "memory")
#define CP_WAIT1()  asm volatile("cp.async.wait_group 1;" ::: "memory")

// ---------------------------------------------------------------------------
// Scratch
// ---------------------------------------------------------------------------
__device__ float g_qkv[(size_t)B_ * O3 * N_];
__device__ __nv_bfloat16 g_Wh[(size_t)B_ * O3 * C_], g_Wl[(size_t)B_ * O3 * C_];
__device__ float g_biasb[B_ * O3];
__device__ float g_mean[B_ * G_], g_rstd[B_ * G_];
__device__ __nv_bfloat16 g_xTh[(size_t)B_ * N_ * C_], g_xTl[(size_t)B_ * N_ * C_];
__device__ __nv_bfloat16 g_kh[(size_t)B_ * C_ * N_],  g_kl[(size_t)B_ * C_ * N_];
__device__ __nv_bfloat16 g_vh[(size_t)B_ * C_ * N_],  g_vl[(size_t)B_ * C_ * N_];
__device__ __nv_bfloat16 g_qTh[(size_t)B_ * N_ * C_], g_qTl[(size_t)B_ * N_ * C_];
__device__ float g_ctx[(size_t)B_ * C_ * C_];
__device__ __nv_bfloat16 g_ctxh[(size_t)B_ * C_ * C_], g_ctxl[(size_t)B_ * C_ * C_];
__device__ float g_Mf[(size_t)B_ * C_ * C_];
__device__ __nv_bfloat16 g_Mh[(size_t)B_ * C_ * C_], g_Ml[(size_t)B_ * C_ * C_];
__device__ __nv_bfloat16 g_pwh[C_ * C_], g_pwl[C_ * C_];

// ---------------------------------------------------------------------------
// Reductions
// ---------------------------------------------------------------------------
__device__ __forceinline__ float warp_sum(float v) {
#pragma unroll
    for (int o = 16; o > 0; o >>= 1) v += __shfl_xor_sync(0xffffffffu, v, o);
    return v;
}
__device__ __forceinline__ float warp_max(float v) {
#pragma unroll
    for (int o = 16; o > 0; o >>= 1) v = fmaxf(v, __shfl_xor_sync(0xffffffffu, v, o));
    return v;
}
__device__ __forceinline__ float block_sum(float v, float* sh) {
    int tid = threadIdx.x, nw = blockDim.x >> 5;
    __syncthreads();
    v = warp_sum(v);
    if ((tid & 31) == 0) sh[tid >> 5] = v;
    __syncthreads();
    if (tid < 32) {
        float w = (tid < nw) ? sh[tid] : 0.f;
        w = warp_sum(w);
        if (tid == 0) sh[0] = w;
    }
    __syncthreads();
    return sh[0];
}
__device__ __forceinline__ float block_max(float v, float* sh) {
    int tid = threadIdx.x, nw = blockDim.x >> 5;
    __syncthreads();
    v = warp_max(v);
    if ((tid & 31) == 0) sh[tid >> 5] = v;
    __syncthreads();
    if (tid < 32) {
        float w = (tid < nw) ? sh[tid] : -3.402823466e38f;
        w = warp_max(w);
        if (tid == 0) sh[0] = w;
    }
    __syncthreads();
    return sh[0];
}

__device__ __forceinline__ void split1(float a, __nv_bfloat16* h, __nv_bfloat16* l) {
    __nv_bfloat16 hh = __float2bfloat16(a);
    *h = hh;
    *l = __float2bfloat16(a - __bfloat162float(hh));
}

// ---------------------------------------------------------------------------
// GroupNorm stats
// ---------------------------------------------------------------------------
__global__ __launch_bounds__(256) void gn_stats_kernel(const float* __restrict__ x) {
    int bg = blockIdx.x;
    const float4* xv = (const float4*)(x + (size_t)bg * CPG * N_);
    const int total = CPG * N_ / 4;
    float s = 0.f, ss = 0.f;
    for (int i = threadIdx.x; i < total; i += 256) {
        float4 v = xv[i];
        s += v.x + v.y + v.z + v.w;
        ss = fmaf(v.x, v.x, fmaf(v.y, v.y, fmaf(v.z, v.z, fmaf(v.w, v.w, ss))));
    }
    __shared__ float sh[32];
    s  = block_sum(s, sh);
    ss = block_sum(ss, sh);
    if (threadIdx.x == 0) {
        const float inv = 1.f / (float)(CPG * N_);
        float m = s * inv;
        g_mean[bg] = m;
        g_rstd[bg] = rsqrtf(ss * inv - m * m + EPSV);
    }
}

// ---------------------------------------------------------------------------
// Fold GN into qkv weights; emit bf16 hi/lo + fp32 bias
// ---------------------------------------------------------------------------
__global__ __launch_bounds__(128) void prep_w_kernel(
    const float* __restrict__ qkv_w, const float* __restrict__ qkv_b,
    const float* __restrict__ gn_scale, const float* __restrict__ gn_bias) {
    int bo = blockIdx.x;
    int b = bo / O3, o = bo % O3;
    float qs = (o < C_) ? QSCALE : 1.f;
    const float* wrow = qkv_w + (size_t)o * C_;
    __nv_bfloat16* wh = g_Wh + (size_t)bo * C_;
    __nv_bfloat16* wl = g_Wl + (size_t)bo * C_;
    float acc = 0.f;
    for (int c = threadIdx.x; c < C_; c += 128) {
        int g = c >> 6;
        float rstd = g_rstd[b * G_ + g];
        float mean = g_mean[b * G_ + g];
        float a = rstd * gn_scale[c];
        float d = gn_bias[c] - mean * a;
        float w = wrow[c];
        split1(w * a * qs, wh + c, wl + c);
        acc = fmaf(w, d, acc);
    }
    __shared__ float sh[32];
    acc = block_sum(acc, sh);
    if (threadIdx.x == 0) g_biasb[bo] = qs * (qkv_b[o] + acc);
}

// ---------------------------------------------------------------------------
// Generic contiguous fp32 -> bf16 hi/lo split
// ---------------------------------------------------------------------------
__global__ __launch_bounds__(256) void split_kernel(
    const float* __restrict__ in, __nv_bfloat16* __restrict__ hi,
    __nv_bfloat16* __restrict__ lo, size_t n4) {
    size_t i = (size_t)blockIdx.x * 256 + threadIdx.x;
    if (i >= n4) return;
    float4 v = ((const float4*)in)[i];
    __nv_bfloat16 h0, h1, h2, h3, l0, l1, l2, l3;
    split1(v.x, &h0, &l0); split1(v.y, &h1, &l1);
    split1(v.z, &h2, &l2); split1(v.w, &h3, &l3);
    __nv_bfloat162* oh = (__nv_bfloat162*)(hi + i * 4);
    __nv_bfloat162* ol = (__nv_bfloat162*)(lo + i * 4);
    oh[0] = __halves2bfloat162(h0, h1); oh[1] = __halves2bfloat162(h2, h3);
    ol[0] = __halves2bfloat162(l0, l1); ol[1] = __halves2bfloat162(l2, l3);
}

// v slab split (strided inside g_qkv)
__global__ __launch_bounds__(256) void split_v_kernel(
    const float* __restrict__ qkv, __nv_bfloat16* __restrict__ hi,
    __nv_bfloat16* __restrict__ lo) {
    size_t i = (size_t)blockIdx.x * 256 + threadIdx.x;
    const size_t per = (size_t)C_ * N_ / 4;
    int b = (int)(i / per);
    size_t r = i - (size_t)b * per;
    float4 v = *(const float4*)(qkv + (size_t)b * O3 * N_ + (size_t)2 * C_ * N_ + r * 4);
    __nv_bfloat16 h0, h1, h2, h3, l0, l1, l2, l3;
    split1(v.x, &h0, &l0); split1(v.y, &h1, &l1);
    split1(v.z, &h2, &l2); split1(v.w, &h3, &l3);
    size_t o = (size_t)b * C_ * N_ + r * 4;
    __nv_bfloat162* oh = (__nv_bfloat162*)(hi + o);
    __nv_bfloat162* ol = (__nv_bfloat162*)(lo + o);
    oh[0] = __halves2bfloat162(h0, h1); oh[1] = __halves2bfloat162(h2, h3);
    ol[0] = __halves2bfloat162(l0, l1); ol[1] = __halves2bfloat162(l2, l3);
}

// ---------------------------------------------------------------------------
// Transpose [C, N] plane -> [N, C] + split to bf16 hi/lo
// ---------------------------------------------------------------------------
__global__ __launch_bounds__(256) void tsplit_kernel(
    const float* __restrict__ in, size_t plane_stride,
    __nv_bfloat16* __restrict__ ohi, __nv_bfloat16* __restrict__ olo) {
    __shared__ float t[32][33];
    int b = blockIdx.z;
    const float* ip = in + (size_t)b * plane_stride;
    int n0 = blockIdx.x * 32, c0 = blockIdx.y * 32;
    for (int j = threadIdx.y; j < 32; j += 8)
        t[j][threadIdx.x] = ip[(size_t)(c0 + j) * N_ + n0 + threadIdx.x];
    __syncthreads();
    size_t ob = (size_t)b * N_ * C_;
    for (int j = threadIdx.y; j < 32; j += 8) {
        float v = t[threadIdx.x][j];
        size_t o = ob + (size_t)(n0 + j) * C_ + c0 + threadIdx.x;
        split1(v, ohi + o, olo + o);
    }
}

// ---------------------------------------------------------------------------
// Row softmax on k slab + emit bf16 hi/lo
// ---------------------------------------------------------------------------
__global__ __launch_bounds__(256) void softmax_split_kernel(
    const float* __restrict__ qkv, __nv_bfloat16* __restrict__ khi,
    __nv_bfloat16* __restrict__ klo) {
    int row = blockIdx.x;
    int b = row / C_, d = row % C_;
    const float4* p = (const float4*)(qkv + ((size_t)b * O3 + C_ + d) * N_);
    const int tid = threadIdx.x;
    float4 v[4];
    float mx = -3.402823466e38f;
#pragma unroll
    for (int i = 0; i < 4; i++) {
        v[i] = p[tid + i * 256];
        mx = fmaxf(mx, fmaxf(fmaxf(v[i].x, v[i].y), fmaxf(v[i].z, v[i].w)));
    }
    __shared__ float sh[32];
    mx = block_max(mx, sh);
    float s = 0.f;
#pragma unroll
    for (int i = 0; i < 4; i++) {
        v[i].x = __expf(v[i].x - mx); v[i].y = __expf(v[i].y - mx);
        v[i].z = __expf(v[i].z - mx); v[i].w = __expf(v[i].w - mx);
        s += v[i].x + v[i].y + v[i].z + v[i].w;
    }
    s = block_sum(s, sh);
    float inv = 1.f / s;
    size_t ob = ((size_t)b * C_ + d) * N_;
    __nv_bfloat162* oh = (__nv_bfloat162*)(khi + ob);
    __nv_bfloat162* ol = (__nv_bfloat162*)(klo + ob);
#pragma unroll
    for (int i = 0; i < 4; i++) {
        float a0 = v[i].x * inv, a1 = v[i].y * inv, a2 = v[i].z * inv, a3 = v[i].w * inv;
        __nv_bfloat16 h0, h1, h2, h3, l0, l1, l2, l3;
        split1(a0, &h0, &l0); split1(a1, &h1, &l1);
        split1(a2, &h2, &l2); split1(a3, &h3, &l3);
        int idx = (tid + i * 256) * 2;
        oh[idx] = __halves2bfloat162(h0, h1); oh[idx + 1] = __halves2bfloat162(h2, h3);
        ol[idx] = __halves2bfloat162(l0, l1); ol[idx + 1] = __halves2bfloat162(l2, l3);
    }
}

// ---------------------------------------------------------------------------
// HMMA bf16x3 NT GEMM: D[m,n] = sum_k A[m,k]*B[n,k] (fp32 out)
// Block 128x128x32, 8 warps (2x4), warp tile 64x32, double-buffered cp.async.
// SMEM row stride = 40 bf16 (80B) -> conflict-free ldmatrix.
// ---------------------------------------------------------------------------
#define LDS_   40
#define T_SZ   (128 * LDS_ * 2)        // 10240 B per tensor tile
#define STAGE  (4 * T_SZ)              // Ah | Al | Bh | Bl
#define SMEMB  (2 * STAGE)             // 81920 B

__device__ __forceinline__ void ld_tile_async(
    const __nv_bfloat16* __restrict__ g, int ldk, uint32_t sbase, int tid) {
#pragma unroll
    for (int i = 0; i < 2; ++i) {
        int idx = tid + i * 256;               // 0..511
        int row = idx >> 2, ch = idx & 3;
        CP_ASYNC16(sbase + row * (LDS_ * 2) + ch * 16,
                   g + (size_t)row * ldk + ch * 8);
    }
}

__global__ __launch_bounds__(256, 1) void hmma_nt_kernel(
    const __nv_bfloat16* __restrict__ Ahi, const __nv_bfloat16* __restrict__ Alo,
    int lda, size_t sA,
    const __nv_bfloat16* __restrict__ Bhi, const __nv_bfloat16* __restrict__ Blo,
    int ldb, size_t sB,
    float* __restrict__ Cc, int ldc, size_t sC,
    const float* __restrict__ bias, int sBias,
    const float* __restrict__ resid, size_t sR,
    int K) {
    extern __shared__ char smem[];
    const uint32_t sb = smem_u32(smem);
    const int tid = threadIdx.x;
    const int wid = tid >> 5, lane = tid & 31;
    const int wm = wid & 1, wn = wid >> 1;    // 2 x 4 warp grid
    const int bz = blockIdx.z;
    const int m0 = blockIdx.y * 128, n0 = blockIdx.x * 128;

    const __nv_bfloat16* gAh = Ahi + (size_t)bz * sA + (size_t)m0 * lda;
    const __nv_bfloat16* gAl = Alo + (size_t)bz * sA + (size_t)m0 * lda;
    const __nv_bfloat16* gBh = Bhi + (size_t)bz * sB + (size_t)n0 * ldb;
    const __nv_bfloat16* gBl = Blo + (size_t)bz * sB + (size_t)n0 * ldb;

    float acc[4][4][4] = {};

    const int nt = K >> 5;                    // K / 32
    // prologue
    {
        uint32_t st = sb;
        ld_tile_async(gAh, lda, st,            tid);
        ld_tile_async(gAl, lda, st + T_SZ,     tid);
        ld_tile_async(gBh, ldb, st + 2 * T_SZ, tid);
        ld_tile_async(gBl, ldb, st + 3 * T_SZ, tid);
        CP_COMMIT();
    }

    // fragment base addresses (lane-dependent, stage-relative)
    const int l16 = lane & 15;
    const int a_m = wm * 64 + l16;            // + mi*16
    const int a_k = (lane >> 4) * 8;          // + ks*16
    const int b_n = wn * 32 + (l16 & 7);      // + ni*8
    const int b_k = ((l16 >> 3) & 1) * 8;     // + ks*16

    for (int kt = 0; kt < nt; ++kt) {
        if (kt + 1 < nt) {
            const __nv_bfloat16* pAh = gAh + ((kt + 1) << 5);
            const __nv_bfloat16* pAl = gAl + ((kt + 1) << 5);
            const __nv_bfloat16* pBh = gBh + ((kt + 1) << 5);
            const __nv_bfloat16* pBl = gBl + ((kt + 1) << 5);
            uint32_t st = sb + ((kt + 1) & 1) * STAGE;
            ld_tile_async(pAh, lda, st,            tid);
            ld_tile_async(pAl, lda, st + T_SZ,     tid);
            ld_tile_async(pBh, ldb, st + 2 * T_SZ, tid);
            ld_tile_async(pBl, ldb, st + 3 * T_SZ, tid);
            CP_COMMIT();
            CP_WAIT1();
        } else {
            CP_WAIT0();
        }
        __syncthreads();

        const uint32_t st = sb + (kt & 1) * STAGE;
#pragma unroll
        for (int ks = 0; ks < 2; ++ks) {
            uint32_t ah[4][4], al[4][4], bh[4][2], bl[4][2];
            const int kk = ks * 16;
#pragma unroll
            for (int mi = 0; mi < 4; ++mi) {
                uint32_t ao = st + (a_m + mi * 16) * (LDS_ * 2) + (kk + a_k) * 2;
                ldsm_x4(ah[mi], ao);
                ldsm_x4(al[mi], ao + T_SZ);
            }
#pragma unroll
            for (int ni = 0; ni < 4; ++ni) {
                uint32_t bo = st + 2 * T_SZ + (b_n + ni * 8) * (LDS_ * 2) + (kk + b_k) * 2;
                ldsm_x2(bh[ni], bo);
                ldsm_x2(bl[ni], bo + T_SZ);
            }
#pragma unroll
            for (int mi = 0; mi < 4; ++mi)
#pragma unroll
                for (int ni = 0; ni < 4; ++ni) {
                    mma16816(acc[mi][ni], ah[mi], bh[ni]);
                    mma16816(acc[mi][ni], ah[mi], bl[ni]);
                    mma16816(acc[mi][ni], al[mi], bh[ni]);
                }
        }
        __syncthreads();
    }

    // Epilogue
    float* Cb = Cc + (size_t)bz * sC;
    const float* Rb = resid ? resid + (size_t)bz * sR : nullptr;
    const int r_in = lane >> 2;
    const int c_in = (lane & 3) * 2;
#pragma unroll
    for (int mi = 0; mi < 4; ++mi) {
        int row0 = m0 + wm * 64 + mi * 16 + r_in;
        int row1 = row0 + 8;
        float b0 = bias ? bias[bz * sBias + row0] : 0.f;
        float b1 = bias ? bias[bz * sBias + row1] : 0.f;
#pragma unroll
        for (int ni = 0; ni < 4; ++ni) {
            int col = n0 + wn * 32 + ni * 8 + c_in;
            float2 v0, v1;
            v0.x = acc[mi][ni][0] + b0; v0.y = acc[mi][ni][1] + b0;
            v1.x = acc[mi][ni][2] + b1; v1.y = acc[mi][ni][3] + b1;
            if (Rb) {
                float2 r0 = *(const float2*)(Rb + (size_t)row0 * ldc + col);
                float2 r1 = *(const float2*)(Rb + (size_t)row1 * ldc + col);
                v0.x += r0.x; v0.y += r0.y;
                v1.x += r1.x; v1.y += r1.y;
            }
            *(float2*)(Cb + (size_t)row0 * ldc + col) = v0;
            *(float2*)(Cb + (size_t)row1 * ldc + col) = v1;
        }
    }
}

// ---------------------------------------------------------------------------
// Launch sequence
// ---------------------------------------------------------------------------
extern "C" void kernel_launch(void* const* d_in, const int* in_sizes, int n_in,
                              void* d_out, int out_size) {
    const float* x        = (const float*)d_in[0];
    const float* qkv_w    = (const float*)d_in[1];
    const float* qkv_b    = (const float*)d_in[2];
    const float* proj_w   = (const float*)d_in[3];
    const float* proj_b   = (const float*)d_in[4];
    const float* gn_scale = (const float*)d_in[5];
    const float* gn_bias  = (const float*)d_in[6];
    float* out = (float*)d_out;

    cudaFuncSetAttribute(hmma_nt_kernel, cudaFuncAttributeMaxDynamicSharedMemorySize, SMEMB);

    float *qkv, *biasb, *ctx, *Mf;
    __nv_bfloat16 *Wh, *Wl, *xTh, *xTl, *kh, *kl, *vh, *vl, *qTh, *qTl;
    __nv_bfloat16 *ctxh, *ctxl, *Mh, *Ml, *pwh, *pwl;
    cudaGetSymbolAddress((void**)&qkv, g_qkv);
    cudaGetSymbolAddress((void**)&biasb, g_biasb);
    cudaGetSymbolAddress((void**)&ctx, g_ctx);
    cudaGetSymbolAddress((void**)&Mf, g_Mf);
    cudaGetSymbolAddress((void**)&Wh, g_Wh);   cudaGetSymbolAddress((void**)&Wl, g_Wl);
    cudaGetSymbolAddress((void**)&xTh, g_xTh); cudaGetSymbolAddress((void**)&xTl, g_xTl);
    cudaGetSymbolAddress((void**)&kh, g_kh);   cudaGetSymbolAddress((void**)&kl, g_kl);
    cudaGetSymbolAddress((void**)&vh, g_vh);   cudaGetSymbolAddress((void**)&vl, g_vl);
    cudaGetSymbolAddress((void**)&qTh, g_qTh); cudaGetSymbolAddress((void**)&qTl, g_qTl);
    cudaGetSymbolAddress((void**)&ctxh, g_ctxh); cudaGetSymbolAddress((void**)&ctxl, g_ctxl);
    cudaGetSymbolAddress((void**)&Mh, g_Mh);   cudaGetSymbolAddress((void**)&Ml, g_Ml);
    cudaGetSymbolAddress((void**)&pwh, g_pwh); cudaGetSymbolAddress((void**)&pwl, g_pwl);

    // 1) GN stats + weight folding/splitting
    gn_stats_kernel<<<B_ * G_, 256>>>(x);
    prep_w_kernel<<<B_ * O3, 128>>>(qkv_w, qkv_b, gn_scale, gn_bias);
    split_kernel<<<(C_ * C_ / 4 + 255) / 256, 256>>>(proj_w, pwh, pwl, C_ * C_ / 4);
    // 2) x -> xT (token-major) bf16 splits
    tsplit_kernel<<<dim3(N_ / 32, C_ / 32, B_), dim3(32, 8)>>>(x, (size_t)C_ * N_, xTh, xTl);
    // 3) qkv[o,n] = Wb[o,c] . xT[n,c]   (M=1536, N=4096, K=512)
    hmma_nt_kernel<<<dim3(N_ / 128, O3 / 128, B_), 256, SMEMB>>>(
        Wh, Wl, C_, (size_t)O3 * C_,
        xTh, xTl, C_, (size_t)N_ * C_,
        qkv, N_, (size_t)O3 * N_,
        biasb, O3, nullptr, 0, C_);
    // 4) softmax(k) + splits; v split; q -> qT split
    softmax_split_kernel<<<B_ * C_, 256>>>(qkv, kh, kl);
    split_v_kernel<<<(int)((size_t)B_ * C_ * N_ / 4 / 256), 256>>>(qkv, vh, vl);
    tsplit_kernel<<<dim3(N_ / 32, C_ / 32, B_), dim3(32, 8)>>>(qkv, (size_t)O3 * N_, qTh, qTl);
    // 5) ctx[d,e] = k_sm[d,n] . v[e,n]  (M=N=512, K=4096)
    hmma_nt_kernel<<<dim3(C_ / 128, C_ / 128, B_), 256, SMEMB>>>(
        kh, kl, N_, (size_t)C_ * N_,
        vh, vl, N_, (size_t)C_ * N_,
        ctx, C_, (size_t)C_ * C_,
        nullptr, 0, nullptr, 0, N_);
    split_kernel<<<(int)((size_t)B_ * C_ * C_ / 4 / 256), 256>>>(ctx, ctxh, ctxl, (size_t)B_ * C_ * C_ / 4);
    // 6) M[o,d] = proj_w[o,e] . ctx[d,e]  (M=N=K=512, A batch-shared)
    hmma_nt_kernel<<<dim3(C_ / 128, C_ / 128, B_), 256, SMEMB>>>(
        pwh, pwl, C_, 0,
        ctxh, ctxl, C_, (size_t)C_ * C_,
        Mf, C_, (size_t)C_ * C_,
        nullptr, 0, nullptr, 0, C_);
    split_kernel<<<(int)((size_t)B_ * C_ * C_ / 4 / 256), 256>>>(Mf, Mh, Ml, (size_t)B_ * C_ * C_ / 4);
    // 7) out[o,n] = M[o,d] . qT[n,d] + proj_b + x  (M=512, N=4096, K=512)
    hmma_nt_kernel<<<dim3(N_ / 128, C_ / 128, B_), 256, SMEMB>>>(
        Mh, Ml, C_, (size_t)C_ * C_,
        qTh, qTl, C_, (size_t)N_ * C_,
        out, N_, (size_t)C_ * N_,
        proj_b, 0, x, (size_t)C_ * N_, C_);
}

// round 4
// speedup vs baseline: 2.8548x; 1.3127x over previous
#include <cuda_runtime.h>
#include <cuda_fp16.h>
#include <cstdint>
#include <math.h>

// Problem constants
#define B_   8
#define C_   512
#define N_   4096
#define G_   8
#define CPG  64
#define O3   1536
#define EPSV 1e-6f
#define QSCALE 0.04419417382415922f   // 512^-0.5

// ---------------------------------------------------------------------------
// PTX helpers (base ISA: ldmatrix / mma.sync / cp.async)
// ---------------------------------------------------------------------------
__device__ __forceinline__ uint32_t smem_u32(const void* p) {
    uint32_t a;
    asm("{ .reg .u64 t; cvta.to.shared.u64 t, %1; cvt.u32.u64 %0, t; }" : "=r"(a) : "l"(p));
    return a;
}
__device__ __forceinline__ void ldsm_x4(uint32_t (&r)[4], uint32_t addr) {
    asm volatile("ldmatrix.sync.aligned.m8n8.x4.shared.b16 {%0,%1,%2,%3}, [%4];"
        : "=r"(r[0]), "=r"(r[1]), "=r"(r[2]), "=r"(r[3]) : "r"(addr));
}
__device__ __forceinline__ void ldsm_x2(uint32_t (&r)[2], uint32_t addr) {
    asm volatile("ldmatrix.sync.aligned.m8n8.x2.shared.b16 {%0,%1}, [%2];"
        : "=r"(r[0]), "=r"(r[1]) : "r"(addr));
}
__device__ __forceinline__ void mma16816(float (&d)[4], const uint32_t (&a)[4],
                                         const uint32_t (&b)[2]) {
    asm volatile(
        "mma.sync.aligned.m16n8k16.row.col.f32.f16.f16.f32 "
        "{%0,%1,%2,%3}, {%4,%5,%6,%7}, {%8,%9}, {%0,%1,%2,%3};"
        : "+f"(d[0]), "+f"(d[1]), "+f"(d[2]), "+f"(d[3])
        : "r"(a[0]), "r"(a[1]), "r"(a[2]), "r"(a[3]), "r"(b[0]), "r"(b[1]));
}
#define CP_ASYNC16(dst, src) \
    asm volatile("cp.async.cg.shared.global [%0], [%1], 16;" :: "r"(dst), "l"(src))
#define CP_COMMIT() asm volatile("cp.async.commit_group;" ::: "memory")
#define CP_WAIT0()  asm volatile("cp.async.wait_group 0;" ::: "memory")
#define CP_WAIT1()  asm volatile("cp.async.wait_group 1;" ::: "memory")

// ---------------------------------------------------------------------------
// Scratch (fp16 everywhere; no fp32 intermediate slabs)
// ---------------------------------------------------------------------------
__device__ __half g_Wh[(size_t)B_ * O3 * C_], g_Wl[(size_t)B_ * O3 * C_];
__device__ float  g_biasb[B_ * O3];
__device__ float  g_mean[B_ * G_], g_rstd[B_ * G_];
__device__ __half g_xTh[(size_t)B_ * N_ * C_], g_xTl[(size_t)B_ * N_ * C_];
__device__ __half g_kh[(size_t)B_ * C_ * N_],  g_kl[(size_t)B_ * C_ * N_];
__device__ __half g_vh[(size_t)B_ * C_ * N_];
__device__ __half g_qTh[(size_t)B_ * N_ * C_];
__device__ __half g_ctxh[(size_t)B_ * C_ * C_];
__device__ __half g_Mh[(size_t)B_ * C_ * C_], g_Ml[(size_t)B_ * C_ * C_];
__device__ __half g_pwh[C_ * C_], g_pwl[C_ * C_];

// ---------------------------------------------------------------------------
// Reductions
// ---------------------------------------------------------------------------
__device__ __forceinline__ float warp_sum(float v) {
#pragma unroll
    for (int o = 16; o > 0; o >>= 1) v += __shfl_xor_sync(0xffffffffu, v, o);
    return v;
}
__device__ __forceinline__ float warp_max(float v) {
#pragma unroll
    for (int o = 16; o > 0; o >>= 1) v = fmaxf(v, __shfl_xor_sync(0xffffffffu, v, o));
    return v;
}
__device__ __forceinline__ float block_sum(float v, float* sh) {
    int tid = threadIdx.x, nw = blockDim.x >> 5;
    __syncthreads();
    v = warp_sum(v);
    if ((tid & 31) == 0) sh[tid >> 5] = v;
    __syncthreads();
    if (tid < 32) {
        float w = (tid < nw) ? sh[tid] : 0.f;
        w = warp_sum(w);
        if (tid == 0) sh[0] = w;
    }
    __syncthreads();
    return sh[0];
}
__device__ __forceinline__ float block_max(float v, float* sh) {
    int tid = threadIdx.x, nw = blockDim.x >> 5;
    __syncthreads();
    v = warp_max(v);
    if ((tid & 31) == 0) sh[tid >> 5] = v;
    __syncthreads();
    if (tid < 32) {
        float w = (tid < nw) ? sh[tid] : -3.402823466e38f;
        w = warp_max(w);
        if (tid == 0) sh[0] = w;
    }
    __syncthreads();
    return sh[0];
}

__device__ __forceinline__ void split1h(float a, __half* h, __half* l) {
    __half hh = __float2half_rn(a);
    *h = hh;
    *l = __float2half_rn(a - __half2float(hh));
}

// ---------------------------------------------------------------------------
// GroupNorm stats
// ---------------------------------------------------------------------------
__global__ __launch_bounds__(256) void gn_stats_kernel(const float* __restrict__ x) {
    int bg = blockIdx.x;
    const float4* xv = (const float4*)(x + (size_t)bg * CPG * N_);
    const int total = CPG * N_ / 4;
    float s = 0.f, ss = 0.f;
    for (int i = threadIdx.x; i < total; i += 256) {
        float4 v = xv[i];
        s += v.x + v.y + v.z + v.w;
        ss = fmaf(v.x, v.x, fmaf(v.y, v.y, fmaf(v.z, v.z, fmaf(v.w, v.w, ss))));
    }
    __shared__ float sh[32];
    s  = block_sum(s, sh);
    ss = block_sum(ss, sh);
    if (threadIdx.x == 0) {
        const float inv = 1.f / (float)(CPG * N_);
        float m = s * inv;
        g_mean[bg] = m;
        g_rstd[bg] = rsqrtf(ss * inv - m * m + EPSV);
    }
}

// ---------------------------------------------------------------------------
// Fold GN (+q scale) into qkv weights; emit fp16 hi/lo + fp32 bias
// ---------------------------------------------------------------------------
__global__ __launch_bounds__(128) void prep_w_kernel(
    const float* __restrict__ qkv_w, const float* __restrict__ qkv_b,
    const float* __restrict__ gn_scale, const float* __restrict__ gn_bias) {
    int bo = blockIdx.x;
    int b = bo / O3, o = bo % O3;
    float qs = (o < C_) ? QSCALE : 1.f;
    const float* wrow = qkv_w + (size_t)o * C_;
    __half* wh = g_Wh + (size_t)bo * C_;
    __half* wl = g_Wl + (size_t)bo * C_;
    float acc = 0.f;
    for (int c = threadIdx.x; c < C_; c += 128) {
        int g = c >> 6;
        float rstd = g_rstd[b * G_ + g];
        float mean = g_mean[b * G_ + g];
        float a = rstd * gn_scale[c];
        float d = gn_bias[c] - mean * a;
        float w = wrow[c];
        split1h(w * a * qs, wh + c, wl + c);
        acc = fmaf(w, d, acc);
    }
    __shared__ float sh[32];
    acc = block_sum(acc, sh);
    if (threadIdx.x == 0) g_biasb[bo] = qs * (qkv_b[o] + acc);
}

// ---------------------------------------------------------------------------
// Contiguous fp32 -> fp16 hi/lo split (proj_w)
// ---------------------------------------------------------------------------
__global__ __launch_bounds__(256) void split_kernel(
    const float* __restrict__ in, __half* __restrict__ hi,
    __half* __restrict__ lo, size_t n4) {
    size_t i = (size_t)blockIdx.x * 256 + threadIdx.x;
    if (i >= n4) return;
    float4 v = ((const float4*)in)[i];
    __half h0, h1, h2, h3, l0, l1, l2, l3;
    split1h(v.x, &h0, &l0); split1h(v.y, &h1, &l1);
    split1h(v.z, &h2, &l2); split1h(v.w, &h3, &l3);
    __half2* oh = (__half2*)(hi + i * 4);
    __half2* ol = (__half2*)(lo + i * 4);
    oh[0] = __halves2half2(h0, h1); oh[1] = __halves2half2(h2, h3);
    ol[0] = __halves2half2(l0, l1); ol[1] = __halves2half2(l2, l3);
}

// ---------------------------------------------------------------------------
// Transpose x [C,N] -> xT [N,C] with fp16 hi/lo split
// ---------------------------------------------------------------------------
__global__ __launch_bounds__(256) void tsplit_kernel(
    const float* __restrict__ in, size_t plane_stride,
    __half* __restrict__ ohi, __half* __restrict__ olo) {
    __shared__ float t[32][33];
    int b = blockIdx.z;
    const float* ip = in + (size_t)b * plane_stride;
    int n0 = blockIdx.x * 32, c0 = blockIdx.y * 32;
    for (int j = threadIdx.y; j < 32; j += 8)
        t[j][threadIdx.x] = ip[(size_t)(c0 + j) * N_ + n0 + threadIdx.x];
    __syncthreads();
    size_t ob = (size_t)b * N_ * C_;
    for (int j = threadIdx.y; j < 32; j += 8) {
        float v = t[threadIdx.x][j];
        size_t o = ob + (size_t)(n0 + j) * C_ + c0 + threadIdx.x;
        split1h(v, ohi + o, olo + o);
    }
}

// ---------------------------------------------------------------------------
// Row softmax, in place on fp16 hi/lo k slab
// ---------------------------------------------------------------------------
__global__ __launch_bounds__(256) void softmax_kernel(
    __half* __restrict__ kh, __half* __restrict__ kl) {
    int row = blockIdx.x;                      // 0 .. B_*C_-1
    __half2* ph = (__half2*)(kh + (size_t)row * N_);
    __half2* pl = (__half2*)(kl + (size_t)row * N_);
    const int tid = threadIdx.x;
    float2 v[8];
    float mx = -3.402823466e38f;
#pragma unroll
    for (int i = 0; i < 8; i++) {
        float2 h = __half22float2(ph[tid + i * 256]);
        float2 l = __half22float2(pl[tid + i * 256]);
        v[i].x = h.x + l.x; v[i].y = h.y + l.y;
        mx = fmaxf(mx, fmaxf(v[i].x, v[i].y));
    }
    __shared__ float sh[32];
    mx = block_max(mx, sh);
    float s = 0.f;
#pragma unroll
    for (int i = 0; i < 8; i++) {
        v[i].x = __expf(v[i].x - mx); v[i].y = __expf(v[i].y - mx);
        s += v[i].x + v[i].y;
    }
    s = block_sum(s, sh);
    float inv = 1.f / s;
#pragma unroll
    for (int i = 0; i < 8; i++) {
        float a0 = v[i].x * inv, a1 = v[i].y * inv;
        __half h0, h1, l0, l1;
        split1h(a0, &h0, &l0); split1h(a1, &h1, &l1);
        ph[tid + i * 256] = __halves2half2(h0, h1);
        pl[tid + i * 256] = __halves2half2(l0, l1);
    }
}

// ---------------------------------------------------------------------------
// HMMA fp16x2 NT GEMM: D[m,n] = sum_k (Ahi+Alo)[m,k] * B[n,k]  (fp32 accum)
// Block 128x128x32, 8 warps (2x4), warp tile 64x32, double-buffered cp.async.
// Output modes: fp32 (+row bias + resid) | fp16 split | fp16 single;
// bias_mode: 0 none, 1 per-row, 2 per-col.
// ---------------------------------------------------------------------------
#define LDS_   40
#define T_SZ   (128 * LDS_ * 2)        // 10240 B per tensor tile
#define STAGE  (3 * T_SZ)              // Ah | Al | B
#define SMEMB  (2 * STAGE)             // 61440 B

__device__ __forceinline__ void ld_tile_async(
    const __half* __restrict__ g, int ldk, uint32_t sbase, int tid) {
#pragma unroll
    for (int i = 0; i < 2; ++i) {
        int idx = tid + i * 256;               // 0..511
        int row = idx >> 2, ch = idx & 3;
        CP_ASYNC16(sbase + row * (LDS_ * 2) + ch * 16,
                   g + (size_t)row * ldk + ch * 8);
    }
}

__global__ __launch_bounds__(256, 1) void hmma_nt_kernel(
    const __half* __restrict__ Ahi, const __half* __restrict__ Alo,
    int lda, size_t sA,
    const __half* __restrict__ Bs, int ldb, size_t sB,
    float* __restrict__ Cf, __half* __restrict__ Chi, __half* __restrict__ Clo,
    int ldc, size_t sC,
    const float* __restrict__ bias, int bias_mode, int sBias,
    const float* __restrict__ resid, size_t sR,
    int K) {
    extern __shared__ char smem[];
    const uint32_t sb = smem_u32(smem);
    const int tid = threadIdx.x;
    const int wid = tid >> 5, lane = tid & 31;
    const int wm = wid & 1, wn = wid >> 1;    // 2 x 4 warp grid
    const int bz = blockIdx.z;
    const int m0 = blockIdx.y * 128, n0 = blockIdx.x * 128;

    const __half* gAh = Ahi + (size_t)bz * sA + (size_t)m0 * lda;
    const __half* gAl = Alo + (size_t)bz * sA + (size_t)m0 * lda;
    const __half* gB  = Bs  + (size_t)bz * sB + (size_t)n0 * ldb;

    float acc[4][4][4] = {};

    const int nt = K >> 5;                    // K / 32
    {
        ld_tile_async(gAh, lda, sb,            tid);
        ld_tile_async(gAl, lda, sb + T_SZ,     tid);
        ld_tile_async(gB,  ldb, sb + 2 * T_SZ, tid);
        CP_COMMIT();
    }

    const int l16 = lane & 15;
    const int a_m = wm * 64 + l16;
    const int a_k = (lane >> 4) * 8;
    const int b_n = wn * 32 + (l16 & 7);
    const int b_k = ((l16 >> 3) & 1) * 8;

    for (int kt = 0; kt < nt; ++kt) {
        if (kt + 1 < nt) {
            uint32_t st = sb + ((kt + 1) & 1) * STAGE;
            const int ko = (kt + 1) << 5;
            ld_tile_async(gAh + ko, lda, st,            tid);
            ld_tile_async(gAl + ko, lda, st + T_SZ,     tid);
            ld_tile_async(gB  + ko, ldb, st + 2 * T_SZ, tid);
            CP_COMMIT();
            CP_WAIT1();
        } else {
            CP_WAIT0();
        }
        __syncthreads();

        const uint32_t st = sb + (kt & 1) * STAGE;
#pragma unroll
        for (int ks = 0; ks < 2; ++ks) {
            uint32_t ah[4][4], al[4][4], bb[4][2];
            const int kk = ks * 16;
#pragma unroll
            for (int mi = 0; mi < 4; ++mi) {
                uint32_t ao = st + (a_m + mi * 16) * (LDS_ * 2) + (kk + a_k) * 2;
                ldsm_x4(ah[mi], ao);
                ldsm_x4(al[mi], ao + T_SZ);
            }
#pragma unroll
            for (int ni = 0; ni < 4; ++ni) {
                uint32_t bo = st + 2 * T_SZ + (b_n + ni * 8) * (LDS_ * 2) + (kk + b_k) * 2;
                ldsm_x2(bb[ni], bo);
            }
#pragma unroll
            for (int mi = 0; mi < 4; ++mi)
#pragma unroll
                for (int ni = 0; ni < 4; ++ni) {
                    mma16816(acc[mi][ni], ah[mi], bb[ni]);
                    mma16816(acc[mi][ni], al[mi], bb[ni]);
                }
        }
        __syncthreads();
    }

    // Epilogue
    const int r_in = lane >> 2;
    const int c_in = (lane & 3) * 2;
    const float* bp = bias ? bias + bz * sBias : nullptr;
#pragma unroll
    for (int mi = 0; mi < 4; ++mi) {
        int row0 = m0 + wm * 64 + mi * 16 + r_in;
        int row1 = row0 + 8;
        float rb0 = 0.f, rb1 = 0.f;
        if (bias_mode == 1) { rb0 = bp[row0]; rb1 = bp[row1]; }
#pragma unroll
        for (int ni = 0; ni < 4; ++ni) {
            int col = n0 + wn * 32 + ni * 8 + c_in;
            float cb0 = 0.f, cb1 = 0.f;
            if (bias_mode == 2) { cb0 = bp[col]; cb1 = bp[col + 1]; }
            float v00 = acc[mi][ni][0] + rb0 + cb0;
            float v01 = acc[mi][ni][1] + rb0 + cb1;
            float v10 = acc[mi][ni][2] + rb1 + cb0;
            float v11 = acc[mi][ni][3] + rb1 + cb1;
            if (Cf) {
                float* Cb = Cf + (size_t)bz * sC;
                if (resid) {
                    const float* Rb = resid + (size_t)bz * sR;
                    float2 r0 = *(const float2*)(Rb + (size_t)row0 * ldc + col);
                    float2 r1 = *(const float2*)(Rb + (size_t)row1 * ldc + col);
                    v00 += r0.x; v01 += r0.y; v10 += r1.x; v11 += r1.y;
                }
                *(float2*)(Cb + (size_t)row0 * ldc + col) = make_float2(v00, v01);
                *(float2*)(Cb + (size_t)row1 * ldc + col) = make_float2(v10, v11);
            } else if (Clo) {
                __half h00, h01, h10, h11, l00, l01, l10, l11;
                split1h(v00, &h00, &l00); split1h(v01, &h01, &l01);
                split1h(v10, &h10, &l10); split1h(v11, &h11, &l11);
                __half* Hb = Chi + (size_t)bz * sC;
                __half* Lb = Clo + (size_t)bz * sC;
                *(__half2*)(Hb + (size_t)row0 * ldc + col) = __halves2half2(h00, h01);
                *(__half2*)(Hb + (size_t)row1 * ldc + col) = __halves2half2(h10, h11);
                *(__half2*)(Lb + (size_t)row0 * ldc + col) = __halves2half2(l00, l01);
                *(__half2*)(Lb + (size_t)row1 * ldc + col) = __halves2half2(l10, l11);
            } else {
                __half* Hb = Chi + (size_t)bz * sC;
                *(__half2*)(Hb + (size_t)row0 * ldc + col) =
                    __halves2half2(__float2half_rn(v00), __float2half_rn(v01));
                *(__half2*)(Hb + (size_t)row1 * ldc + col) =
                    __halves2half2(__float2half_rn(v10), __float2half_rn(v11));
            }
        }
    }
}

// ---------------------------------------------------------------------------
// Launch sequence
// ---------------------------------------------------------------------------
extern "C" void kernel_launch(void* const* d_in, const int* in_sizes, int n_in,
                              void* d_out, int out_size) {
    const float* x        = (const float*)d_in[0];
    const float* qkv_w    = (const float*)d_in[1];
    const float* qkv_b    = (const float*)d_in[2];
    const float* proj_w   = (const float*)d_in[3];
    const float* proj_b   = (const float*)d_in[4];
    const float* gn_scale = (const float*)d_in[5];
    const float* gn_bias  = (const float*)d_in[6];
    float* out = (float*)d_out;

    cudaFuncSetAttribute(hmma_nt_kernel, cudaFuncAttributeMaxDynamicSharedMemorySize, SMEMB);

    float *biasb;
    __half *Wh, *Wl, *xTh, *xTl, *kh, *kl, *vh, *qTh, *ctxh, *Mh, *Ml, *pwh, *pwl;
    cudaGetSymbolAddress((void**)&biasb, g_biasb);
    cudaGetSymbolAddress((void**)&Wh, g_Wh);   cudaGetSymbolAddress((void**)&Wl, g_Wl);
    cudaGetSymbolAddress((void**)&xTh, g_xTh); cudaGetSymbolAddress((void**)&xTl, g_xTl);
    cudaGetSymbolAddress((void**)&kh, g_kh);   cudaGetSymbolAddress((void**)&kl, g_kl);
    cudaGetSymbolAddress((void**)&vh, g_vh);
    cudaGetSymbolAddress((void**)&qTh, g_qTh);
    cudaGetSymbolAddress((void**)&ctxh, g_ctxh);
    cudaGetSymbolAddress((void**)&Mh, g_Mh);   cudaGetSymbolAddress((void**)&Ml, g_Ml);
    cudaGetSymbolAddress((void**)&pwh, g_pwh); cudaGetSymbolAddress((void**)&pwl, g_pwl);

    // 1) GN stats, weight folding (fp16 hi/lo), proj_w split
    gn_stats_kernel<<<B_ * G_, 256>>>(x);
    prep_w_kernel<<<B_ * O3, 128>>>(qkv_w, qkv_b, gn_scale, gn_bias);
    split_kernel<<<(C_ * C_ / 4 + 255) / 256, 256>>>(proj_w, pwh, pwl, C_ * C_ / 4);
    // 2) x -> xT fp16 hi/lo
    tsplit_kernel<<<dim3(N_ / 32, C_ / 32, B_), dim3(32, 8)>>>(x, (size_t)C_ * N_, xTh, xTl);
    // 3) k[d,n] = Wk(split) . xT(single) + bias  -> fp16 split out
    hmma_nt_kernel<<<dim3(N_ / 128, C_ / 128, B_), 256, SMEMB>>>(
        Wh + (size_t)C_ * C_, Wl + (size_t)C_ * C_, C_, (size_t)O3 * C_,
        xTh, C_, (size_t)N_ * C_,
        nullptr, kh, kl, N_, (size_t)C_ * N_,
        biasb + C_, 1, O3, nullptr, 0, C_);
    // 4) v[e,n] = Wv(split) . xT(single) + bias  -> fp16 single out
    hmma_nt_kernel<<<dim3(N_ / 128, C_ / 128, B_), 256, SMEMB>>>(
        Wh + (size_t)2 * C_ * C_, Wl + (size_t)2 * C_ * C_, C_, (size_t)O3 * C_,
        xTh, C_, (size_t)N_ * C_,
        nullptr, vh, nullptr, N_, (size_t)C_ * N_,
        biasb + 2 * C_, 1, O3, nullptr, 0, C_);
    // 5) qT[n,o] = xT(split) . Wq(single) + bias[col] -> fp16 single out
    hmma_nt_kernel<<<dim3(C_ / 128, N_ / 128, B_), 256, SMEMB>>>(
        xTh, xTl, C_, (size_t)N_ * C_,
        Wh, C_, (size_t)O3 * C_,
        nullptr, qTh, nullptr, C_, (size_t)N_ * C_,
        biasb, 2, O3, nullptr, 0, C_);
    // 6) softmax over tokens on k (in place, fp16 hi/lo)
    softmax_kernel<<<B_ * C_, 256>>>(kh, kl);
    // 7) ctx[d,e] = k_sm(split) . v(single)  -> fp16 single out
    hmma_nt_kernel<<<dim3(C_ / 128, C_ / 128, B_), 256, SMEMB>>>(
        kh, kl, N_, (size_t)C_ * N_,
        vh, N_, (size_t)C_ * N_,
        nullptr, ctxh, nullptr, C_, (size_t)C_ * C_,
        nullptr, 0, 0, nullptr, 0, N_);
    // 8) M[o,d] = proj_w(split) . ctx(single)  -> fp16 split out
    hmma_nt_kernel<<<dim3(C_ / 128, C_ / 128, B_), 256, SMEMB>>>(
        pwh, pwl, C_, 0,
        ctxh, C_, (size_t)C_ * C_,
        nullptr, Mh, Ml, C_, (size_t)C_ * C_,
        nullptr, 0, 0, nullptr, 0, C_);
    // 9) out[o,n] = M(split) . qT(single) + proj_b + x  -> fp32
    hmma_nt_kernel<<<dim3(N_ / 128, C_ / 128, B_), 256, SMEMB>>>(
        Mh, Ml, C_, (size_t)C_ * C_,
        qTh, C_, (size_t)N_ * C_,
        out, nullptr, nullptr, N_, (size_t)C_ * N_,
        proj_b, 1, 0, x, (size_t)C_ * N_, C_);
}

// round 5
// speedup vs baseline: 4.6430x; 1.6263x over previous
#include <cuda_runtime.h>
#include <cuda_fp16.h>
#include <cstdint>
#include <math.h>

// Problem constants
#define B_   8
#define C_   512
#define N_   4096
#define G_   8
#define CPG  64
#define O3   1536
#define EPSV 1e-6f
#define QSCALE 0.04419417382415922f   // 512^-0.5

// ---------------------------------------------------------------------------
// PTX helpers
// ---------------------------------------------------------------------------
__device__ __forceinline__ uint32_t smem_u32(const void* p) {
    uint32_t a;
    asm("{ .reg .u64 t; cvta.to.shared.u64 t, %1; cvt.u32.u64 %0, t; }" : "=r"(a) : "l"(p));
    return a;
}
__device__ __forceinline__ void ldsm_x4(uint32_t (&r)[4], uint32_t addr) {
    asm volatile("ldmatrix.sync.aligned.m8n8.x4.shared.b16 {%0,%1,%2,%3}, [%4];"
        : "=r"(r[0]), "=r"(r[1]), "=r"(r[2]), "=r"(r[3]) : "r"(addr));
}
__device__ __forceinline__ void mma16816(float (&d)[4], const uint32_t (&a)[4],
                                         uint32_t b0, uint32_t b1) {
    asm volatile(
        "mma.sync.aligned.m16n8k16.row.col.f32.f16.f16.f32 "
        "{%0,%1,%2,%3}, {%4,%5,%6,%7}, {%8,%9}, {%0,%1,%2,%3};"
        : "+f"(d[0]), "+f"(d[1]), "+f"(d[2]), "+f"(d[3])
        : "r"(a[0]), "r"(a[1]), "r"(a[2]), "r"(a[3]), "r"(b0), "r"(b1));
}
#define CP_ASYNC16(dst, src) \
    asm volatile("cp.async.cg.shared.global [%0], [%1], 16;" :: "r"(dst), "l"(src))
#define CP_COMMIT() asm volatile("cp.async.commit_group;" ::: "memory")
#define CP_WAIT0()  asm volatile("cp.async.wait_group 0;" ::: "memory")
#define CP_WAIT1()  asm volatile("cp.async.wait_group 1;" ::: "memory")

// ---------------------------------------------------------------------------
// Scratch
// ---------------------------------------------------------------------------
__device__ __half g_Wh[(size_t)B_ * O3 * C_];
__device__ float  g_biasb[B_ * O3];
__device__ float  g_mean[B_ * G_], g_rstd[B_ * G_];
__device__ __half g_xTh[(size_t)B_ * N_ * C_];
__device__ float  g_kf[(size_t)B_ * C_ * N_];        // fp32 k logits
__device__ __half g_kh[(size_t)B_ * C_ * N_];        // softmaxed k
__device__ __half g_vh[(size_t)B_ * C_ * N_];
__device__ __half g_qTh[(size_t)B_ * N_ * C_];
__device__ __half g_ctxh[(size_t)B_ * C_ * C_];
__device__ __half g_Mh[(size_t)B_ * C_ * C_];
__device__ __half g_pwh[C_ * C_];

// ---------------------------------------------------------------------------
// Reductions
// ---------------------------------------------------------------------------
__device__ __forceinline__ float warp_sum(float v) {
#pragma unroll
    for (int o = 16; o > 0; o >>= 1) v += __shfl_xor_sync(0xffffffffu, v, o);
    return v;
}
__device__ __forceinline__ float warp_max(float v) {
#pragma unroll
    for (int o = 16; o > 0; o >>= 1) v = fmaxf(v, __shfl_xor_sync(0xffffffffu, v, o));
    return v;
}
__device__ __forceinline__ float block_sum(float v, float* sh) {
    int tid = threadIdx.x, nw = blockDim.x >> 5;
    __syncthreads();
    v = warp_sum(v);
    if ((tid & 31) == 0) sh[tid >> 5] = v;
    __syncthreads();
    if (tid < 32) {
        float w = (tid < nw) ? sh[tid] : 0.f;
        w = warp_sum(w);
        if (tid == 0) sh[0] = w;
    }
    __syncthreads();
    return sh[0];
}
__device__ __forceinline__ float block_max(float v, float* sh) {
    int tid = threadIdx.x, nw = blockDim.x >> 5;
    __syncthreads();
    v = warp_max(v);
    if ((tid & 31) == 0) sh[tid >> 5] = v;
    __syncthreads();
    if (tid < 32) {
        float w = (tid < nw) ? sh[tid] : -3.402823466e38f;
        w = warp_max(w);
        if (tid == 0) sh[0] = w;
    }
    __syncthreads();
    return sh[0];
}

// ---------------------------------------------------------------------------
// GroupNorm stats
// ---------------------------------------------------------------------------
__global__ __launch_bounds__(256) void gn_stats_kernel(const float* __restrict__ x) {
    int bg = blockIdx.x;
    const float4* xv = (const float4*)(x + (size_t)bg * CPG * N_);
    const int total = CPG * N_ / 4;
    float s = 0.f, ss = 0.f;
    for (int i = threadIdx.x; i < total; i += 256) {
        float4 v = xv[i];
        s += v.x + v.y + v.z + v.w;
        ss = fmaf(v.x, v.x, fmaf(v.y, v.y, fmaf(v.z, v.z, fmaf(v.w, v.w, ss))));
    }
    __shared__ float sh[32];
    s  = block_sum(s, sh);
    ss = block_sum(ss, sh);
    if (threadIdx.x == 0) {
        const float inv = 1.f / (float)(CPG * N_);
        float m = s * inv;
        g_mean[bg] = m;
        g_rstd[bg] = rsqrtf(ss * inv - m * m + EPSV);
    }
}

// ---------------------------------------------------------------------------
// Fold GN (+q scale) into qkv weights -> fp16; fold means into bias (fp32)
// ---------------------------------------------------------------------------
__global__ __launch_bounds__(128) void prep_w_kernel(
    const float* __restrict__ qkv_w, const float* __restrict__ qkv_b,
    const float* __restrict__ gn_scale, const float* __restrict__ gn_bias) {
    int bo = blockIdx.x;
    int b = bo / O3, o = bo % O3;
    float qs = (o < C_) ? QSCALE : 1.f;
    const float* wrow = qkv_w + (size_t)o * C_;
    __half* wh = g_Wh + (size_t)bo * C_;
    float acc = 0.f;
    for (int c = threadIdx.x; c < C_; c += 128) {
        int g = c >> 6;
        float rstd = g_rstd[b * G_ + g];
        float mean = g_mean[b * G_ + g];
        float a = rstd * gn_scale[c];
        float d = gn_bias[c] - mean * a;
        float w = wrow[c];
        wh[c] = __float2half_rn(w * a * qs);
        acc = fmaf(w, d, acc);
    }
    __shared__ float sh[32];
    acc = block_sum(acc, sh);
    if (threadIdx.x == 0) g_biasb[bo] = qs * (qkv_b[o] + acc);
}

// ---------------------------------------------------------------------------
// fp32 -> fp16 convert (proj_w)
// ---------------------------------------------------------------------------
__global__ __launch_bounds__(256) void f2h_kernel(
    const float* __restrict__ in, __half* __restrict__ out, size_t n4) {
    size_t i = (size_t)blockIdx.x * 256 + threadIdx.x;
    if (i >= n4) return;
    float4 v = ((const float4*)in)[i];
    __half2* o = (__half2*)(out + i * 4);
    o[0] = __halves2half2(__float2half_rn(v.x), __float2half_rn(v.y));
    o[1] = __halves2half2(__float2half_rn(v.z), __float2half_rn(v.w));
}

// ---------------------------------------------------------------------------
// Transpose x [C,N] -> xT [N,C] fp16 (half2 coalesced writes)
// grid (N/32, C/64, B), block (32,8)
// ---------------------------------------------------------------------------
__global__ __launch_bounds__(256) void tconv_kernel(
    const float* __restrict__ in, __half* __restrict__ out) {
    __shared__ float t[64][33];
    int b = blockIdx.z;
    const float* ip = in + (size_t)b * C_ * N_;
    int n0 = blockIdx.x * 32, c0 = blockIdx.y * 64;
    int tx = threadIdx.x, ty = threadIdx.y;
    for (int j = ty; j < 64; j += 8)
        t[j][tx] = ip[(size_t)(c0 + j) * N_ + n0 + tx];
    __syncthreads();
    __half* op = out + (size_t)b * N_ * C_;
    for (int j = ty; j < 32; j += 8) {
        int n = n0 + j;
        int c = c0 + tx * 2;
        __half2 v = __halves2half2(__float2half_rn(t[tx * 2][j]),
                                   __float2half_rn(t[tx * 2 + 1][j]));
        *(__half2*)(op + (size_t)n * C_ + c) = v;
    }
}

// ---------------------------------------------------------------------------
// Row softmax: fp32 logits -> fp16 probabilities
// ---------------------------------------------------------------------------
__global__ __launch_bounds__(256) void softmax_kernel(
    const float* __restrict__ kf, __half* __restrict__ kh) {
    int row = blockIdx.x;                      // 0 .. B_*C_-1
    const float4* p = (const float4*)(kf + (size_t)row * N_);
    __half2* o = (__half2*)(kh + (size_t)row * N_);
    const int tid = threadIdx.x;
    float4 v[4];
    float mx = -3.402823466e38f;
#pragma unroll
    for (int i = 0; i < 4; i++) {
        v[i] = p[tid + i * 256];
        mx = fmaxf(mx, fmaxf(fmaxf(v[i].x, v[i].y), fmaxf(v[i].z, v[i].w)));
    }
    __shared__ float sh[32];
    mx = block_max(mx, sh);
    float s = 0.f;
#pragma unroll
    for (int i = 0; i < 4; i++) {
        v[i].x = __expf(v[i].x - mx); v[i].y = __expf(v[i].y - mx);
        v[i].z = __expf(v[i].z - mx); v[i].w = __expf(v[i].w - mx);
        s += v[i].x + v[i].y + v[i].z + v[i].w;
    }
    s = block_sum(s, sh);
    float inv = 1.f / s;
#pragma unroll
    for (int i = 0; i < 4; i++) {
        int idx = (tid + i * 256) * 2;
        o[idx]     = __halves2half2(__float2half_rn(v[i].x * inv), __float2half_rn(v[i].y * inv));
        o[idx + 1] = __halves2half2(__float2half_rn(v[i].z * inv), __float2half_rn(v[i].w * inv));
    }
}

// ---------------------------------------------------------------------------
// HMMA fp16 NT GEMM: D[m,n] = sum_k A[m,k]*B[n,k] (fp32 accum)
// Block 128x128x32, 4 warps (2x2), warp tile 64x64, double-buffered cp.async.
// Output: fp32 (+bias +resid) or fp16. bias_mode: 0 none, 1 per-row, 2 per-col.
// ---------------------------------------------------------------------------
#define LDS_   40
#define T_SZ   (128 * LDS_ * 2)        // 10240 B per tensor tile
#define STAGE  (2 * T_SZ)              // A | B
#define SMEMB  (2 * STAGE)             // 40960 B

__device__ __forceinline__ void ld_tile_async(
    const __half* __restrict__ g, int ldk, uint32_t sbase, int tid) {
#pragma unroll
    for (int i = 0; i < 4; ++i) {
        int idx = tid + i * 128;               // 0..511
        int row = idx >> 2, ch = idx & 3;
        CP_ASYNC16(sbase + row * (LDS_ * 2) + ch * 16,
                   g + (size_t)row * ldk + ch * 8);
    }
}

__global__ __launch_bounds__(128) void hmma_nt_kernel(
    const __half* __restrict__ A, int lda, size_t sA,
    const __half* __restrict__ Bs, int ldb, size_t sB,
    float* __restrict__ Cf, __half* __restrict__ Ch, int ldc, size_t sC,
    const float* __restrict__ bias, int bias_mode, int sBias,
    const float* __restrict__ resid, size_t sR,
    int K) {
    extern __shared__ char smem[];
    const uint32_t sb = smem_u32(smem);
    const int tid = threadIdx.x;
    const int wid = tid >> 5, lane = tid & 31;
    const int wm = wid & 1, wn = wid >> 1;    // 2 x 2 warp grid
    const int bz = blockIdx.z;
    const int m0 = blockIdx.y * 128, n0 = blockIdx.x * 128;

    const __half* gA = A  + (size_t)bz * sA + (size_t)m0 * lda;
    const __half* gB = Bs + (size_t)bz * sB + (size_t)n0 * ldb;

    float acc[4][8][4] = {};

    const int nt = K >> 5;                    // K / 32
    {
        ld_tile_async(gA, lda, sb,        tid);
        ld_tile_async(gB, ldb, sb + T_SZ, tid);
        CP_COMMIT();
    }

    const int a_m  = wm * 64 + (lane & 15);          // + mi*16
    const int a_k  = (lane >> 4) * 8;                // + ks*16
    const int b_nr = wn * 64 + (lane & 7) + ((lane >> 4) << 3);  // + nj*16
    const int b_k  = ((lane >> 3) & 1) * 8;          // + ks*16

    for (int kt = 0; kt < nt; ++kt) {
        if (kt + 1 < nt) {
            uint32_t st = sb + ((kt + 1) & 1) * STAGE;
            const int ko = (kt + 1) << 5;
            ld_tile_async(gA + ko, lda, st,        tid);
            ld_tile_async(gB + ko, ldb, st + T_SZ, tid);
            CP_COMMIT();
            CP_WAIT1();
        } else {
            CP_WAIT0();
        }
        __syncthreads();

        const uint32_t st = sb + (kt & 1) * STAGE;
#pragma unroll
        for (int ks = 0; ks < 2; ++ks) {
            const int kk = ks * 16;
            uint32_t ah[4][4], bb[4][4];
#pragma unroll
            for (int mi = 0; mi < 4; ++mi)
                ldsm_x4(ah[mi], st + (a_m + mi * 16) * (LDS_ * 2) + (kk + a_k) * 2);
#pragma unroll
            for (int nj = 0; nj < 4; ++nj)
                ldsm_x4(bb[nj], st + T_SZ + (b_nr + nj * 16) * (LDS_ * 2) + (kk + b_k) * 2);
#pragma unroll
            for (int mi = 0; mi < 4; ++mi)
#pragma unroll
                for (int nj = 0; nj < 4; ++nj) {
                    mma16816(acc[mi][2 * nj],     ah[mi], bb[nj][0], bb[nj][1]);
                    mma16816(acc[mi][2 * nj + 1], ah[mi], bb[nj][2], bb[nj][3]);
                }
        }
        __syncthreads();
    }

    // Epilogue
    const int r_in = lane >> 2;
    const int c_in = (lane & 3) * 2;
    const float* bp = bias ? bias + bz * sBias : nullptr;
#pragma unroll
    for (int mi = 0; mi < 4; ++mi) {
        int row0 = m0 + wm * 64 + mi * 16 + r_in;
        int row1 = row0 + 8;
        float rb0 = 0.f, rb1 = 0.f;
        if (bias_mode == 1) { rb0 = bp[row0]; rb1 = bp[row1]; }
#pragma unroll
        for (int ni = 0; ni < 8; ++ni) {
            int col = n0 + wn * 64 + ni * 8 + c_in;
            float cb0 = 0.f, cb1 = 0.f;
            if (bias_mode == 2) { cb0 = bp[col]; cb1 = bp[col + 1]; }
            float v00 = acc[mi][ni][0] + rb0 + cb0;
            float v01 = acc[mi][ni][1] + rb0 + cb1;
            float v10 = acc[mi][ni][2] + rb1 + cb0;
            float v11 = acc[mi][ni][3] + rb1 + cb1;
            if (Cf) {
                float* Cb = Cf + (size_t)bz * sC;
                if (resid) {
                    const float* Rb = resid + (size_t)bz * sR;
                    float2 r0 = *(const float2*)(Rb + (size_t)row0 * ldc + col);
                    float2 r1 = *(const float2*)(Rb + (size_t)row1 * ldc + col);
                    v00 += r0.x; v01 += r0.y; v10 += r1.x; v11 += r1.y;
                }
                *(float2*)(Cb + (size_t)row0 * ldc + col) = make_float2(v00, v01);
                *(float2*)(Cb + (size_t)row1 * ldc + col) = make_float2(v10, v11);
            } else {
                __half* Hb = Ch + (size_t)bz * sC;
                *(__half2*)(Hb + (size_t)row0 * ldc + col) =
                    __halves2half2(__float2half_rn(v00), __float2half_rn(v01));
                *(__half2*)(Hb + (size_t)row1 * ldc + col) =
                    __halves2half2(__float2half_rn(v10), __float2half_rn(v11));
            }
        }
    }
}

// ---------------------------------------------------------------------------
// Launch sequence
// ---------------------------------------------------------------------------
extern "C" void kernel_launch(void* const* d_in, const int* in_sizes, int n_in,
                              void* d_out, int out_size) {
    const float* x        = (const float*)d_in[0];
    const float* qkv_w    = (const float*)d_in[1];
    const float* qkv_b    = (const float*)d_in[2];
    const float* proj_w   = (const float*)d_in[3];
    const float* proj_b   = (const float*)d_in[4];
    const float* gn_scale = (const float*)d_in[5];
    const float* gn_bias  = (const float*)d_in[6];
    float* out = (float*)d_out;

    cudaFuncSetAttribute(hmma_nt_kernel, cudaFuncAttributeMaxDynamicSharedMemorySize, SMEMB);

    float *biasb, *kf;
    __half *Wh, *xTh, *kh, *vh, *qTh, *ctxh, *Mh, *pwh;
    cudaGetSymbolAddress((void**)&biasb, g_biasb);
    cudaGetSymbolAddress((void**)&kf, g_kf);
    cudaGetSymbolAddress((void**)&Wh, g_Wh);
    cudaGetSymbolAddress((void**)&xTh, g_xTh);
    cudaGetSymbolAddress((void**)&kh, g_kh);
    cudaGetSymbolAddress((void**)&vh, g_vh);
    cudaGetSymbolAddress((void**)&qTh, g_qTh);
    cudaGetSymbolAddress((void**)&ctxh, g_ctxh);
    cudaGetSymbolAddress((void**)&Mh, g_Mh);
    cudaGetSymbolAddress((void**)&pwh, g_pwh);

    // 1) GN stats, weight folding (fp16), proj_w convert
    gn_stats_kernel<<<B_ * G_, 256>>>(x);
    prep_w_kernel<<<B_ * O3, 128>>>(qkv_w, qkv_b, gn_scale, gn_bias);
    f2h_kernel<<<(C_ * C_ / 4 + 255) / 256, 256>>>(proj_w, pwh, C_ * C_ / 4);
    // 2) x -> xT fp16
    tconv_kernel<<<dim3(N_ / 32, C_ / 64, B_), dim3(32, 8)>>>(x, xTh);
    // 3) k logits (fp32 out, for softmax precision): k[d,n] = Wk . xT + bias
    hmma_nt_kernel<<<dim3(N_ / 128, C_ / 128, B_), 128, SMEMB>>>(
        Wh + (size_t)C_ * C_, C_, (size_t)O3 * C_,
        xTh, C_, (size_t)N_ * C_,
        kf, nullptr, N_, (size_t)C_ * N_,
        biasb + C_, 1, O3, nullptr, 0, C_);
    // 4) v[e,n] = Wv . xT + bias -> fp16
    hmma_nt_kernel<<<dim3(N_ / 128, C_ / 128, B_), 128, SMEMB>>>(
        Wh + (size_t)2 * C_ * C_, C_, (size_t)O3 * C_,
        xTh, C_, (size_t)N_ * C_,
        nullptr, vh, N_, (size_t)C_ * N_,
        biasb + 2 * C_, 1, O3, nullptr, 0, C_);
    // 5) qT[n,o] = xT . Wq + bias[col] -> fp16
    hmma_nt_kernel<<<dim3(C_ / 128, N_ / 128, B_), 128, SMEMB>>>(
        xTh, C_, (size_t)N_ * C_,
        Wh, C_, (size_t)O3 * C_,
        nullptr, qTh, C_, (size_t)N_ * C_,
        biasb, 2, O3, nullptr, 0, C_);
    // 6) softmax over tokens (fp32 in, fp16 out)
    softmax_kernel<<<B_ * C_, 256>>>(kf, kh);
    // 7) ctx[d,e] = k_sm . v^T -> fp16
    hmma_nt_kernel<<<dim3(C_ / 128, C_ / 128, B_), 128, SMEMB>>>(
        kh, N_, (size_t)C_ * N_,
        vh, N_, (size_t)C_ * N_,
        nullptr, ctxh, C_, (size_t)C_ * C_,
        nullptr, 0, 0, nullptr, 0, N_);
    // 8) M[o,d] = proj_w . ctx^T -> fp16  (A batch-shared)
    hmma_nt_kernel<<<dim3(C_ / 128, C_ / 128, B_), 128, SMEMB>>>(
        pwh, C_, 0,
        ctxh, C_, (size_t)C_ * C_,
        nullptr, Mh, C_, (size_t)C_ * C_,
        nullptr, 0, 0, nullptr, 0, C_);
    // 9) out[o,n] = M . qT^T + proj_b + x -> fp32
    hmma_nt_kernel<<<dim3(N_ / 128, C_ / 128, B_), 128, SMEMB>>>(
        Mh, C_, (size_t)C_ * C_,
        qTh, C_, (size_t)N_ * C_,
        out, nullptr, N_, (size_t)C_ * N_,
        proj_b, 1, 0, x, (size_t)C_ * N_, C_);
}

// round 6
// speedup vs baseline: 5.4372x; 1.1711x over previous
#include <cuda_runtime.h>
#include <cuda_fp16.h>
#include <cstdint>
#include <math.h>

// Problem constants
#define B_   8
#define C_   512
#define N_   4096
#define G_   8
#define CPG  64
#define O3   1536
#define EPSV 1e-6f
#define QSCALE 0.04419417382415922f   // 512^-0.5

// ---------------------------------------------------------------------------
// PTX helpers
// ---------------------------------------------------------------------------
__device__ __forceinline__ uint32_t smem_u32(const void* p) {
    uint32_t a;
    asm("{ .reg .u64 t; cvta.to.shared.u64 t, %1; cvt.u32.u64 %0, t; }" : "=r"(a) : "l"(p));
    return a;
}
__device__ __forceinline__ void ldsm_x4(uint32_t (&r)[4], uint32_t addr) {
    asm volatile("ldmatrix.sync.aligned.m8n8.x4.shared.b16 {%0,%1,%2,%3}, [%4];"
        : "=r"(r[0]), "=r"(r[1]), "=r"(r[2]), "=r"(r[3]) : "r"(addr));
}
__device__ __forceinline__ void mma16816(float (&d)[4], const uint32_t (&a)[4],
                                         uint32_t b0, uint32_t b1) {
    asm volatile(
        "mma.sync.aligned.m16n8k16.row.col.f32.f16.f16.f32 "
        "{%0,%1,%2,%3}, {%4,%5,%6,%7}, {%8,%9}, {%0,%1,%2,%3};"
        : "+f"(d[0]), "+f"(d[1]), "+f"(d[2]), "+f"(d[3])
        : "r"(a[0]), "r"(a[1]), "r"(a[2]), "r"(a[3]), "r"(b0), "r"(b1));
}
#define CP_ASYNC16(dst, src) \
    asm volatile("cp.async.cg.shared.global [%0], [%1], 16;" :: "r"(dst), "l"(src))
#define CP_COMMIT() asm volatile("cp.async.commit_group;" ::: "memory")
#define CP_WAIT0()  asm volatile("cp.async.wait_group 0;" ::: "memory")
#define CP_WAIT1()  asm volatile("cp.async.wait_group 1;" ::: "memory")
#define CP_WAIT2()  asm volatile("cp.async.wait_group 2;" ::: "memory")

// ---------------------------------------------------------------------------
// Scratch
// ---------------------------------------------------------------------------
__device__ __half g_Wh[(size_t)B_ * O3 * C_];         // GN-folded qkv weights (fp16)
__device__ float  g_biasb[B_ * O3];                   // folded qkv bias (fp32)
__device__ float  g_mean[B_ * G_], g_rstd[B_ * G_];
__device__ __half g_xTh[(size_t)B_ * N_ * C_];        // x token-major fp16
__device__ __half g_xh [(size_t)B_ * C_ * N_];        // x channel-major fp16
__device__ float  g_kf[(size_t)B_ * C_ * N_];         // k logits fp32
__device__ __half g_kh[(size_t)B_ * C_ * N_];         // softmaxed k fp16
__device__ __half g_kxh[(size_t)B_ * C_ * C_];        // k_sm @ x^T
__device__ __half g_ctxh[(size_t)B_ * C_ * C_];
__device__ __half g_Mh[(size_t)B_ * C_ * C_];
__device__ __half g_Eh[(size_t)B_ * C_ * C_];         // M @ Wq
__device__ __half g_wqTh[(size_t)B_ * C_ * C_];       // Wq transposed [c,o]
__device__ __half g_pwh[C_ * C_];
__device__ float  g_fb[B_ * C_];                      // final fused bias

// ---------------------------------------------------------------------------
// Reductions
// ---------------------------------------------------------------------------
__device__ __forceinline__ float warp_sum(float v) {
#pragma unroll
    for (int o = 16; o > 0; o >>= 1) v += __shfl_xor_sync(0xffffffffu, v, o);
    return v;
}
__device__ __forceinline__ float warp_max(float v) {
#pragma unroll
    for (int o = 16; o > 0; o >>= 1) v = fmaxf(v, __shfl_xor_sync(0xffffffffu, v, o));
    return v;
}
__device__ __forceinline__ float block_sum(float v, float* sh) {
    int tid = threadIdx.x, nw = blockDim.x >> 5;
    __syncthreads();
    v = warp_sum(v);
    if ((tid & 31) == 0) sh[tid >> 5] = v;
    __syncthreads();
    if (tid < 32) {
        float w = (tid < nw) ? sh[tid] : 0.f;
        w = warp_sum(w);
        if (tid == 0) sh[0] = w;
    }
    __syncthreads();
    return sh[0];
}
__device__ __forceinline__ float block_max(float v, float* sh) {
    int tid = threadIdx.x, nw = blockDim.x >> 5;
    __syncthreads();
    v = warp_max(v);
    if ((tid & 31) == 0) sh[tid >> 5] = v;
    __syncthreads();
    if (tid < 32) {
        float w = (tid < nw) ? sh[tid] : -3.402823466e38f;
        w = warp_max(w);
        if (tid == 0) sh[0] = w;
    }
    __syncthreads();
    return sh[0];
}

// ---------------------------------------------------------------------------
// GroupNorm stats
// ---------------------------------------------------------------------------
__global__ __launch_bounds__(256) void gn_stats_kernel(const float* __restrict__ x) {
    int bg = blockIdx.x;
    const float4* xv = (const float4*)(x + (size_t)bg * CPG * N_);
    const int total = CPG * N_ / 4;
    float s = 0.f, ss = 0.f;
    for (int i = threadIdx.x; i < total; i += 256) {
        float4 v = xv[i];
        s += v.x + v.y + v.z + v.w;
        ss = fmaf(v.x, v.x, fmaf(v.y, v.y, fmaf(v.z, v.z, fmaf(v.w, v.w, ss))));
    }
    __shared__ float sh[32];
    s  = block_sum(s, sh);
    ss = block_sum(ss, sh);
    if (threadIdx.x == 0) {
        const float inv = 1.f / (float)(CPG * N_);
        float m = s * inv;
        g_mean[bg] = m;
        g_rstd[bg] = rsqrtf(ss * inv - m * m + EPSV);
    }
}

// ---------------------------------------------------------------------------
// Fold GN (+q scale) into qkv weights -> fp16; fold means into bias (fp32)
// ---------------------------------------------------------------------------
__global__ __launch_bounds__(128) void prep_w_kernel(
    const float* __restrict__ qkv_w, const float* __restrict__ qkv_b,
    const float* __restrict__ gn_scale, const float* __restrict__ gn_bias) {
    int bo = blockIdx.x;
    int b = bo / O3, o = bo % O3;
    float qs = (o < C_) ? QSCALE : 1.f;
    const float* wrow = qkv_w + (size_t)o * C_;
    __half* wh = g_Wh + (size_t)bo * C_;
    float acc = 0.f;
    for (int c = threadIdx.x; c < C_; c += 128) {
        int g = c >> 6;
        float rstd = g_rstd[b * G_ + g];
        float mean = g_mean[b * G_ + g];
        float a = rstd * gn_scale[c];
        float d = gn_bias[c] - mean * a;
        float w = wrow[c];
        wh[c] = __float2half_rn(w * a * qs);
        acc = fmaf(w, d, acc);
    }
    __shared__ float sh[32];
    acc = block_sum(acc, sh);
    if (threadIdx.x == 0) g_biasb[bo] = qs * (qkv_b[o] + acc);
}

// ---------------------------------------------------------------------------
// fp32 -> fp16 convert
// ---------------------------------------------------------------------------
__global__ __launch_bounds__(256) void f2h_kernel(
    const float* __restrict__ in, __half* __restrict__ out, size_t n4) {
    size_t i = (size_t)blockIdx.x * 256 + threadIdx.x;
    if (i >= n4) return;
    float4 v = ((const float4*)in)[i];
    __half2* o = (__half2*)(out + i * 4);
    o[0] = __halves2half2(__float2half_rn(v.x), __float2half_rn(v.y));
    o[1] = __halves2half2(__float2half_rn(v.z), __float2half_rn(v.w));
}

// ---------------------------------------------------------------------------
// Transpose x [C,N] -> xT [N,C] fp16
// ---------------------------------------------------------------------------
__global__ __launch_bounds__(256) void tconv_kernel(
    const float* __restrict__ in, __half* __restrict__ out) {
    __shared__ float t[64][33];
    int b = blockIdx.z;
    const float* ip = in + (size_t)b * C_ * N_;
    int n0 = blockIdx.x * 32, c0 = blockIdx.y * 64;
    int tx = threadIdx.x, ty = threadIdx.y;
    for (int j = ty; j < 64; j += 8)
        t[j][tx] = ip[(size_t)(c0 + j) * N_ + n0 + tx];
    __syncthreads();
    __half* op = out + (size_t)b * N_ * C_;
    for (int j = ty; j < 32; j += 8) {
        int n = n0 + j;
        int c = c0 + tx * 2;
        __half2 v = __halves2half2(__float2half_rn(t[tx * 2][j]),
                                   __float2half_rn(t[tx * 2 + 1][j]));
        *(__half2*)(op + (size_t)n * C_ + c) = v;
    }
}

// ---------------------------------------------------------------------------
// Transpose q-slab of folded weights: Wq [o,c] -> wqT [c,o]  (fp16, per batch)
// ---------------------------------------------------------------------------
__global__ __launch_bounds__(256) void wqt_kernel() {
    __shared__ __half t[32][33];
    int b = blockIdx.z;
    const __half* W = g_Wh + (size_t)b * O3 * C_;   // q slab = first C_ rows
    __half* outp = g_wqTh + (size_t)b * C_ * C_;
    int c0 = blockIdx.x * 32, o0 = blockIdx.y * 32;
    int tx = threadIdx.x, ty = threadIdx.y;
    for (int j = ty; j < 32; j += 8)
        t[j][tx] = W[(size_t)(o0 + j) * C_ + c0 + tx];
    __syncthreads();
    for (int j = ty; j < 32; j += 8)
        outp[(size_t)(c0 + j) * C_ + o0 + tx] = t[tx][j];
}

// ---------------------------------------------------------------------------
// Row softmax: fp32 logits -> fp16 probabilities
// ---------------------------------------------------------------------------
__global__ __launch_bounds__(256) void softmax_kernel(
    const float* __restrict__ kf, __half* __restrict__ kh) {
    int row = blockIdx.x;
    const float4* p = (const float4*)(kf + (size_t)row * N_);
    __half2* o = (__half2*)(kh + (size_t)row * N_);
    const int tid = threadIdx.x;
    float4 v[4];
    float mx = -3.402823466e38f;
#pragma unroll
    for (int i = 0; i < 4; i++) {
        v[i] = p[tid + i * 256];
        mx = fmaxf(mx, fmaxf(fmaxf(v[i].x, v[i].y), fmaxf(v[i].z, v[i].w)));
    }
    __shared__ float sh[32];
    mx = block_max(mx, sh);
    float s = 0.f;
#pragma unroll
    for (int i = 0; i < 4; i++) {
        v[i].x = __expf(v[i].x - mx); v[i].y = __expf(v[i].y - mx);
        v[i].z = __expf(v[i].z - mx); v[i].w = __expf(v[i].w - mx);
        s += v[i].x + v[i].y + v[i].z + v[i].w;
    }
    s = block_sum(s, sh);
    float inv = 1.f / s;
#pragma unroll
    for (int i = 0; i < 4; i++) {
        int idx = (tid + i * 256) * 2;
        o[idx]     = __halves2half2(__float2half_rn(v[i].x * inv), __float2half_rn(v[i].y * inv));
        o[idx + 1] = __halves2half2(__float2half_rn(v[i].z * inv), __float2half_rn(v[i].w * inv));
    }
}

// ---------------------------------------------------------------------------
// fb[b,o] = proj_b[o] + sum_d M[b,o,d] * bq_b[b,d]   (one warp per row)
// ---------------------------------------------------------------------------
__global__ __launch_bounds__(256) void fb_kernel(const float* __restrict__ proj_b) {
    int r = blockIdx.x * 8 + (threadIdx.x >> 5);    // 0 .. B_*C_-1
    int b = r / C_, o = r % C_;
    const __half* Mrow = g_Mh + ((size_t)b * C_ + o) * C_;
    const float* bq = g_biasb + b * O3;             // q-slab bias
    int lane = threadIdx.x & 31;
    float s = 0.f;
    for (int d = lane; d < C_; d += 32)
        s += __half2float(Mrow[d]) * bq[d];
    s = warp_sum(s);
    if (lane == 0) g_fb[r] = s + proj_b[o];
}

// ---------------------------------------------------------------------------
// HMMA fp16 NT GEMM: D[m,n] = sum_k A[m,k]*B[n,k] (fp32 accum)
// Block 128x128x32, 4 warps (2x2), warp tile 64x64, 4-stage cp.async pipeline.
// Output: fp32 (+bias +resid) or fp16. bias_mode: 0 none, 1 per-row, 2 per-col.
// ---------------------------------------------------------------------------
#define LDS_   40
#define T_SZ   (128 * LDS_ * 2)        // 10240 B per tensor tile
#define STAGE  (2 * T_SZ)              // A | B  = 20480 B
#define NSTG   4
#define SMEMB  (NSTG * STAGE)          // 81920 B

__device__ __forceinline__ void ld_tile_async(
    const __half* __restrict__ g, int ldk, uint32_t sbase, int tid) {
#pragma unroll
    for (int i = 0; i < 4; ++i) {
        int idx = tid + i * 128;               // 0..511
        int row = idx >> 2, ch = idx & 3;
        CP_ASYNC16(sbase + row * (LDS_ * 2) + ch * 16,
                   g + (size_t)row * ldk + ch * 8);
    }
}

__global__ __launch_bounds__(128) void hmma_nt_kernel(
    const __half* __restrict__ A, int lda, size_t sA,
    const __half* __restrict__ Bs, int ldb, size_t sB,
    float* __restrict__ Cf, __half* __restrict__ Ch, int ldc, size_t sC,
    const float* __restrict__ bias, int bias_mode, int sBias,
    const float* __restrict__ resid, size_t sR,
    int K) {
    extern __shared__ char smem[];
    const uint32_t sb = smem_u32(smem);
    const int tid = threadIdx.x;
    const int wid = tid >> 5, lane = tid & 31;
    const int wm = wid & 1, wn = wid >> 1;    // 2 x 2 warp grid
    const int bz = blockIdx.z;
    const int m0 = blockIdx.y * 128, n0 = blockIdx.x * 128;

    const __half* gA = A  + (size_t)bz * sA + (size_t)m0 * lda;
    const __half* gB = Bs + (size_t)bz * sB + (size_t)n0 * ldb;

    float acc[4][8][4] = {};

    const int nt = K >> 5;                    // K / 32
    // prologue: issue stages 0..NSTG-2
#pragma unroll
    for (int s = 0; s < NSTG - 1; ++s) {
        if (s < nt) {
            uint32_t st = sb + s * STAGE;
            ld_tile_async(gA + (s << 5), lda, st,        tid);
            ld_tile_async(gB + (s << 5), ldb, st + T_SZ, tid);
        }
        CP_COMMIT();
    }

    const int a_m  = wm * 64 + (lane & 15);
    const int a_k  = (lane >> 4) * 8;
    const int b_nr = wn * 64 + (lane & 7) + ((lane >> 4) << 3);
    const int b_k  = ((lane >> 3) & 1) * 8;

    for (int kt = 0; kt < nt; ++kt) {
        const int pre = kt + NSTG - 1;
        if (pre < nt) {
            uint32_t st = sb + (pre & (NSTG - 1)) * STAGE;
            ld_tile_async(gA + (pre << 5), lda, st,        tid);
            ld_tile_async(gB + (pre << 5), ldb, st + T_SZ, tid);
        }
        CP_COMMIT();
        const int rem = nt - 1 - kt;
        if (rem >= NSTG - 2) { CP_WAIT2(); }
        else if (rem == 1)   { CP_WAIT1(); }
        else                 { CP_WAIT0(); }
        __syncthreads();

        const uint32_t st = sb + (kt & (NSTG - 1)) * STAGE;
#pragma unroll
        for (int ks = 0; ks < 2; ++ks) {
            const int kk = ks * 16;
            uint32_t ah[4][4], bb[4][4];
#pragma unroll
            for (int mi = 0; mi < 4; ++mi)
                ldsm_x4(ah[mi], st + (a_m + mi * 16) * (LDS_ * 2) + (kk + a_k) * 2);
#pragma unroll
            for (int nj = 0; nj < 4; ++nj)
                ldsm_x4(bb[nj], st + T_SZ + (b_nr + nj * 16) * (LDS_ * 2) + (kk + b_k) * 2);
#pragma unroll
            for (int mi = 0; mi < 4; ++mi)
#pragma unroll
                for (int nj = 0; nj < 4; ++nj) {
                    mma16816(acc[mi][2 * nj],     ah[mi], bb[nj][0], bb[nj][1]);
                    mma16816(acc[mi][2 * nj + 1], ah[mi], bb[nj][2], bb[nj][3]);
                }
        }
        __syncthreads();
    }

    // Epilogue
    const int r_in = lane >> 2;
    const int c_in = (lane & 3) * 2;
    const float* bp = bias ? bias + bz * sBias : nullptr;
#pragma unroll
    for (int mi = 0; mi < 4; ++mi) {
        int row0 = m0 + wm * 64 + mi * 16 + r_in;
        int row1 = row0 + 8;
        float rb0 = 0.f, rb1 = 0.f;
        if (bias_mode == 1) { rb0 = bp[row0]; rb1 = bp[row1]; }
#pragma unroll
        for (int ni = 0; ni < 8; ++ni) {
            int col = n0 + wn * 64 + ni * 8 + c_in;
            float cb0 = 0.f, cb1 = 0.f;
            if (bias_mode == 2) { cb0 = bp[col]; cb1 = bp[col + 1]; }
            float v00 = acc[mi][ni][0] + rb0 + cb0;
            float v01 = acc[mi][ni][1] + rb0 + cb1;
            float v10 = acc[mi][ni][2] + rb1 + cb0;
            float v11 = acc[mi][ni][3] + rb1 + cb1;
            if (Cf) {
                float* Cb = Cf + (size_t)bz * sC;
                if (resid) {
                    const float* Rb = resid + (size_t)bz * sR;
                    float2 r0 = *(const float2*)(Rb + (size_t)row0 * ldc + col);
                    float2 r1 = *(const float2*)(Rb + (size_t)row1 * ldc + col);
                    v00 += r0.x; v01 += r0.y; v10 += r1.x; v11 += r1.y;
                }
                *(float2*)(Cb + (size_t)row0 * ldc + col) = make_float2(v00, v01);
                *(float2*)(Cb + (size_t)row1 * ldc + col) = make_float2(v10, v11);
            } else {
                __half* Hb = Ch + (size_t)bz * sC;
                *(__half2*)(Hb + (size_t)row0 * ldc + col) =
                    __halves2half2(__float2half_rn(v00), __float2half_rn(v01));
                *(__half2*)(Hb + (size_t)row1 * ldc + col) =
                    __halves2half2(__float2half_rn(v10), __float2half_rn(v11));
            }
        }
    }
}

// ---------------------------------------------------------------------------
// Launch sequence
// ---------------------------------------------------------------------------
extern "C" void kernel_launch(void* const* d_in, const int* in_sizes, int n_in,
                              void* d_out, int out_size) {
    const float* x        = (const float*)d_in[0];
    const float* qkv_w    = (const float*)d_in[1];
    const float* qkv_b    = (const float*)d_in[2];
    const float* proj_w   = (const float*)d_in[3];
    const float* proj_b   = (const float*)d_in[4];
    const float* gn_scale = (const float*)d_in[5];
    const float* gn_bias  = (const float*)d_in[6];
    float* out = (float*)d_out;

    cudaFuncSetAttribute(hmma_nt_kernel, cudaFuncAttributeMaxDynamicSharedMemorySize, SMEMB);

    float *biasb, *kf, *fb;
    __half *Wh, *xTh, *xh, *kh, *kxh, *ctxh, *Mh, *Eh, *wqTh, *pwh;
    cudaGetSymbolAddress((void**)&biasb, g_biasb);
    cudaGetSymbolAddress((void**)&kf, g_kf);
    cudaGetSymbolAddress((void**)&fb, g_fb);
    cudaGetSymbolAddress((void**)&Wh, g_Wh);
    cudaGetSymbolAddress((void**)&xTh, g_xTh);
    cudaGetSymbolAddress((void**)&xh, g_xh);
    cudaGetSymbolAddress((void**)&kh, g_kh);
    cudaGetSymbolAddress((void**)&kxh, g_kxh);
    cudaGetSymbolAddress((void**)&ctxh, g_ctxh);
    cudaGetSymbolAddress((void**)&Mh, g_Mh);
    cudaGetSymbolAddress((void**)&Eh, g_Eh);
    cudaGetSymbolAddress((void**)&wqTh, g_wqTh);
    cudaGetSymbolAddress((void**)&pwh, g_pwh);

    // 1) GN stats, weight folding, converts
    gn_stats_kernel<<<B_ * G_, 256>>>(x);
    prep_w_kernel<<<B_ * O3, 128>>>(qkv_w, qkv_b, gn_scale, gn_bias);
    f2h_kernel<<<(C_ * C_ / 4 + 255) / 256, 256>>>(proj_w, pwh, C_ * C_ / 4);
    tconv_kernel<<<dim3(N_ / 32, C_ / 64, B_), dim3(32, 8)>>>(x, xTh);
    f2h_kernel<<<(int)((size_t)B_ * C_ * N_ / 4 / 256), 256>>>(x, xh, (size_t)B_ * C_ * N_ / 4);
    wqt_kernel<<<dim3(C_ / 32, C_ / 32, B_), dim3(32, 8)>>>();
    // 2) k logits (fp32): k[d,n] = Wk . xT + bk
    hmma_nt_kernel<<<dim3(N_ / 128, C_ / 128, B_), 128, SMEMB>>>(
        Wh + (size_t)C_ * C_, C_, (size_t)O3 * C_,
        xTh, C_, (size_t)N_ * C_,
        kf, nullptr, N_, (size_t)C_ * N_,
        biasb + C_, 1, O3, nullptr, 0, C_);
    // 3) softmax over tokens
    softmax_kernel<<<B_ * C_, 256>>>(kf, kh);
    // 4) kx[d,c] = k_sm . x^T   (K=4096)
    hmma_nt_kernel<<<dim3(C_ / 128, C_ / 128, B_), 128, SMEMB>>>(
        kh, N_, (size_t)C_ * N_,
        xh, N_, (size_t)C_ * N_,
        nullptr, kxh, C_, (size_t)C_ * C_,
        nullptr, 0, 0, nullptr, 0, N_);
    // 5) ctx[d,e] = kx . Wv^T + bv[e]
    hmma_nt_kernel<<<dim3(C_ / 128, C_ / 128, B_), 128, SMEMB>>>(
        kxh, C_, (size_t)C_ * C_,
        Wh + (size_t)2 * C_ * C_, C_, (size_t)O3 * C_,
        nullptr, ctxh, C_, (size_t)C_ * C_,
        biasb + 2 * C_, 2, O3, nullptr, 0, C_);
    // 6) M[o,d] = proj_w . ctx^T
    hmma_nt_kernel<<<dim3(C_ / 128, C_ / 128, B_), 128, SMEMB>>>(
        pwh, C_, 0,
        ctxh, C_, (size_t)C_ * C_,
        nullptr, Mh, C_, (size_t)C_ * C_,
        nullptr, 0, 0, nullptr, 0, C_);
    // 7) E[o,c] = M . WqT^T   (= M @ Wq)
    hmma_nt_kernel<<<dim3(C_ / 128, C_ / 128, B_), 128, SMEMB>>>(
        Mh, C_, (size_t)C_ * C_,
        wqTh, C_, (size_t)C_ * C_,
        nullptr, Eh, C_, (size_t)C_ * C_,
        nullptr, 0, 0, nullptr, 0, C_);
    // 8) fb = proj_b + M @ bq
    fb_kernel<<<B_ * C_ / 8, 256>>>(proj_b);
    // 9) out[o,n] = E . xT^T + fb[o] + x
    hmma_nt_kernel<<<dim3(N_ / 128, C_ / 128, B_), 128, SMEMB>>>(
        Eh, C_, (size_t)C_ * C_,
        xTh, C_, (size_t)N_ * C_,
        out, nullptr, N_, (size_t)C_ * N_,
        fb, 1, C_, x, (size_t)C_ * N_, C_);
}

// round 7
// speedup vs baseline: 5.5342x; 1.0179x over previous
#include <cuda_runtime.h>
#include <cuda_fp16.h>
#include <cstdint>
#include <math.h>

// Problem constants
#define B_   8
#define C_   512
#define N_   4096
#define G_   8
#define CPG  64
#define O3   1536
#define EPSV 1e-6f
#define QSCALE 0.04419417382415922f   // 512^-0.5

// ---------------------------------------------------------------------------
// PTX helpers
// ---------------------------------------------------------------------------
__device__ __forceinline__ uint32_t smem_u32(const void* p) {
    uint32_t a;
    asm("{ .reg .u64 t; cvta.to.shared.u64 t, %1; cvt.u32.u64 %0, t; }" : "=r"(a) : "l"(p));
    return a;
}
__device__ __forceinline__ void ldsm_x4(uint32_t (&r)[4], uint32_t addr) {
    asm volatile("ldmatrix.sync.aligned.m8n8.x4.shared.b16 {%0,%1,%2,%3}, [%4];"
        : "=r"(r[0]), "=r"(r[1]), "=r"(r[2]), "=r"(r[3]) : "r"(addr));
}
__device__ __forceinline__ void mma16816(float (&d)[4], const uint32_t (&a)[4],
                                         uint32_t b0, uint32_t b1) {
    asm volatile(
        "mma.sync.aligned.m16n8k16.row.col.f32.f16.f16.f32 "
        "{%0,%1,%2,%3}, {%4,%5,%6,%7}, {%8,%9}, {%0,%1,%2,%3};"
        : "+f"(d[0]), "+f"(d[1]), "+f"(d[2]), "+f"(d[3])
        : "r"(a[0]), "r"(a[1]), "r"(a[2]), "r"(a[3]), "r"(b0), "r"(b1));
}
#define CP_ASYNC16(dst, src) \
    asm volatile("cp.async.cg.shared.global [%0], [%1], 16;" :: "r"(dst), "l"(src))
#define CP_COMMIT() asm volatile("cp.async.commit_group;" ::: "memory")
#define CP_WAIT0()  asm volatile("cp.async.wait_group 0;" ::: "memory")
#define CP_WAIT1()  asm volatile("cp.async.wait_group 1;" ::: "memory")
#define CP_WAIT2()  asm volatile("cp.async.wait_group 2;" ::: "memory")

// ---------------------------------------------------------------------------
// Scratch
// ---------------------------------------------------------------------------
__device__ __half g_Wh[(size_t)B_ * O3 * C_];
__device__ float  g_biasb[B_ * O3];
__device__ float  g_mean[B_ * G_], g_rstd[B_ * G_];
__device__ __half g_xTh[(size_t)B_ * N_ * C_];        // x token-major fp16
__device__ __half g_xh [(size_t)B_ * C_ * N_];        // x channel-major fp16
__device__ float  g_kf[(size_t)B_ * C_ * N_];         // k logits fp32
__device__ __half g_kh[(size_t)B_ * C_ * N_];         // softmaxed k fp16
__device__ __half g_kxh[(size_t)B_ * C_ * C_];        // k_sm @ x^T
__device__ __half g_ctxh[(size_t)B_ * C_ * C_];
__device__ __half g_Mh[(size_t)B_ * C_ * C_];
__device__ __half g_Eh[(size_t)B_ * C_ * C_];         // M @ Wq
__device__ __half g_wqTh[(size_t)B_ * C_ * C_];       // Wq transposed [c,o]
__device__ __half g_pwh[C_ * C_];
__device__ float  g_fb[B_ * C_];                      // final fused bias

// ---------------------------------------------------------------------------
// Reductions
// ---------------------------------------------------------------------------
__device__ __forceinline__ float warp_sum(float v) {
#pragma unroll
    for (int o = 16; o > 0; o >>= 1) v += __shfl_xor_sync(0xffffffffu, v, o);
    return v;
}
__device__ __forceinline__ float warp_max(float v) {
#pragma unroll
    for (int o = 16; o > 0; o >>= 1) v = fmaxf(v, __shfl_xor_sync(0xffffffffu, v, o));
    return v;
}
__device__ __forceinline__ float block_sum(float v, float* sh) {
    int tid = threadIdx.x, nw = blockDim.x >> 5;
    __syncthreads();
    v = warp_sum(v);
    if ((tid & 31) == 0) sh[tid >> 5] = v;
    __syncthreads();
    if (tid < 32) {
        float w = (tid < nw) ? sh[tid] : 0.f;
        w = warp_sum(w);
        if (tid == 0) sh[0] = w;
    }
    __syncthreads();
    return sh[0];
}
__device__ __forceinline__ float block_max(float v, float* sh) {
    int tid = threadIdx.x, nw = blockDim.x >> 5;
    __syncthreads();
    v = warp_max(v);
    if ((tid & 31) == 0) sh[tid >> 5] = v;
    __syncthreads();
    if (tid < 32) {
        float w = (tid < nw) ? sh[tid] : -3.402823466e38f;
        w = warp_max(w);
        if (tid == 0) sh[0] = w;
    }
    __syncthreads();
    return sh[0];
}

// ---------------------------------------------------------------------------
// GroupNorm stats
// ---------------------------------------------------------------------------
__global__ __launch_bounds__(256) void gn_stats_kernel(const float* __restrict__ x) {
    int bg = blockIdx.x;
    const float4* xv = (const float4*)(x + (size_t)bg * CPG * N_);
    const int total = CPG * N_ / 4;
    float s = 0.f, ss = 0.f;
    for (int i = threadIdx.x; i < total; i += 256) {
        float4 v = xv[i];
        s += v.x + v.y + v.z + v.w;
        ss = fmaf(v.x, v.x, fmaf(v.y, v.y, fmaf(v.z, v.z, fmaf(v.w, v.w, ss))));
    }
    __shared__ float sh[32];
    s  = block_sum(s, sh);
    ss = block_sum(ss, sh);
    if (threadIdx.x == 0) {
        const float inv = 1.f / (float)(CPG * N_);
        float m = s * inv;
        g_mean[bg] = m;
        g_rstd[bg] = rsqrtf(ss * inv - m * m + EPSV);
    }
}

// ---------------------------------------------------------------------------
// Fold GN (+q scale) into qkv weights -> fp16; fold means into bias (fp32)
// ---------------------------------------------------------------------------
__global__ __launch_bounds__(128) void prep_w_kernel(
    const float* __restrict__ qkv_w, const float* __restrict__ qkv_b,
    const float* __restrict__ gn_scale, const float* __restrict__ gn_bias) {
    int bo = blockIdx.x;
    int b = bo / O3, o = bo % O3;
    float qs = (o < C_) ? QSCALE : 1.f;
    const float* wrow = qkv_w + (size_t)o * C_;
    __half* wh = g_Wh + (size_t)bo * C_;
    float acc = 0.f;
    for (int c = threadIdx.x; c < C_; c += 128) {
        int g = c >> 6;
        float rstd = g_rstd[b * G_ + g];
        float mean = g_mean[b * G_ + g];
        float a = rstd * gn_scale[c];
        float d = gn_bias[c] - mean * a;
        float w = wrow[c];
        wh[c] = __float2half_rn(w * a * qs);
        acc = fmaf(w, d, acc);
    }
    __shared__ float sh[32];
    acc = block_sum(acc, sh);
    if (threadIdx.x == 0) g_biasb[bo] = qs * (qkv_b[o] + acc);
}

// ---------------------------------------------------------------------------
// fp32 -> fp16 convert
// ---------------------------------------------------------------------------
__global__ __launch_bounds__(256) void f2h_kernel(
    const float* __restrict__ in, __half* __restrict__ out, size_t n4) {
    size_t i = (size_t)blockIdx.x * 256 + threadIdx.x;
    if (i >= n4) return;
    float4 v = ((const float4*)in)[i];
    __half2* o = (__half2*)(out + i * 4);
    o[0] = __halves2half2(__float2half_rn(v.x), __float2half_rn(v.y));
    o[1] = __halves2half2(__float2half_rn(v.z), __float2half_rn(v.w));
}

// ---------------------------------------------------------------------------
// Transpose x [C,N] -> xT [N,C] fp16, AND emit channel-major fp16 copy xh
// grid (N/32, C/64, B), block (32,8)
// ---------------------------------------------------------------------------
__global__ __launch_bounds__(256) void tconv_kernel(
    const float* __restrict__ in, __half* __restrict__ outT,
    __half* __restrict__ outCh) {
    __shared__ float t[64][33];
    int b = blockIdx.z;
    const float* ip = in + (size_t)b * C_ * N_;
    __half* chp = outCh + (size_t)b * C_ * N_;
    int n0 = blockIdx.x * 32, c0 = blockIdx.y * 64;
    int tx = threadIdx.x, ty = threadIdx.y;
    for (int j = ty; j < 64; j += 8) {
        float v = ip[(size_t)(c0 + j) * N_ + n0 + tx];
        t[j][tx] = v;
        chp[(size_t)(c0 + j) * N_ + n0 + tx] = __float2half_rn(v);
    }
    __syncthreads();
    __half* op = outT + (size_t)b * N_ * C_;
    for (int j = ty; j < 32; j += 8) {
        int n = n0 + j;
        int c = c0 + tx * 2;
        __half2 v = __halves2half2(__float2half_rn(t[tx * 2][j]),
                                   __float2half_rn(t[tx * 2 + 1][j]));
        *(__half2*)(op + (size_t)n * C_ + c) = v;
    }
}

// ---------------------------------------------------------------------------
// Transpose q-slab of folded weights: Wq [o,c] -> wqT [c,o]  (fp16, per batch)
// ---------------------------------------------------------------------------
__global__ __launch_bounds__(256) void wqt_kernel() {
    __shared__ __half t[32][33];
    int b = blockIdx.z;
    const __half* W = g_Wh + (size_t)b * O3 * C_;
    __half* outp = g_wqTh + (size_t)b * C_ * C_;
    int c0 = blockIdx.x * 32, o0 = blockIdx.y * 32;
    int tx = threadIdx.x, ty = threadIdx.y;
    for (int j = ty; j < 32; j += 8)
        t[j][tx] = W[(size_t)(o0 + j) * C_ + c0 + tx];
    __syncthreads();
    for (int j = ty; j < 32; j += 8)
        outp[(size_t)(c0 + j) * C_ + o0 + tx] = t[tx][j];
}

// ---------------------------------------------------------------------------
// Row softmax: fp32 logits -> fp16 probabilities
// ---------------------------------------------------------------------------
__global__ __launch_bounds__(256) void softmax_kernel(
    const float* __restrict__ kf, __half* __restrict__ kh) {
    int row = blockIdx.x;
    const float4* p = (const float4*)(kf + (size_t)row * N_);
    __half2* o = (__half2*)(kh + (size_t)row * N_);
    const int tid = threadIdx.x;
    float4 v[4];
    float mx = -3.402823466e38f;
#pragma unroll
    for (int i = 0; i < 4; i++) {
        v[i] = p[tid + i * 256];
        mx = fmaxf(mx, fmaxf(fmaxf(v[i].x, v[i].y), fmaxf(v[i].z, v[i].w)));
    }
    __shared__ float sh[32];
    mx = block_max(mx, sh);
    float s = 0.f;
#pragma unroll
    for (int i = 0; i < 4; i++) {
        v[i].x = __expf(v[i].x - mx); v[i].y = __expf(v[i].y - mx);
        v[i].z = __expf(v[i].z - mx); v[i].w = __expf(v[i].w - mx);
        s += v[i].x + v[i].y + v[i].z + v[i].w;
    }
    s = block_sum(s, sh);
    float inv = 1.f / s;
#pragma unroll
    for (int i = 0; i < 4; i++) {
        int idx = (tid + i * 256) * 2;
        o[idx]     = __halves2half2(__float2half_rn(v[i].x * inv), __float2half_rn(v[i].y * inv));
        o[idx + 1] = __halves2half2(__float2half_rn(v[i].z * inv), __float2half_rn(v[i].w * inv));
    }
}

// ---------------------------------------------------------------------------
// fb[b,o] = proj_b[o] + sum_d M[b,o,d] * bq_b[b,d]
// ---------------------------------------------------------------------------
__global__ __launch_bounds__(256) void fb_kernel(const float* __restrict__ proj_b) {
    int r = blockIdx.x * 8 + (threadIdx.x >> 5);
    int b = r / C_, o = r % C_;
    const __half* Mrow = g_Mh + ((size_t)b * C_ + o) * C_;
    const float* bq = g_biasb + b * O3;
    int lane = threadIdx.x & 31;
    float s = 0.f;
    for (int d = lane; d < C_; d += 32)
        s += __half2float(Mrow[d]) * bq[d];
    s = warp_sum(s);
    if (lane == 0) g_fb[r] = s + proj_b[o];
}

// ---------------------------------------------------------------------------
// Shared GEMM plumbing
// ---------------------------------------------------------------------------
#define LDS_   40
#define NSTG   4

// ---- 128x128 tile kernel -------------------------------------------------
#define T_SZ   (128 * LDS_ * 2)        // 10240 B
#define STAGE  (2 * T_SZ)
#define SMEMB  (NSTG * STAGE)          // 81920 B

__device__ __forceinline__ void ld_tile_async128(
    const __half* __restrict__ g, int ldk, uint32_t sbase, int tid) {
#pragma unroll
    for (int i = 0; i < 4; ++i) {
        int idx = tid + i * 128;
        int row = idx >> 2, ch = idx & 3;
        CP_ASYNC16(sbase + row * (LDS_ * 2) + ch * 16,
                   g + (size_t)row * ldk + ch * 8);
    }
}

__global__ __launch_bounds__(128) void hmma_nt_kernel(
    const __half* __restrict__ A, int lda, size_t sA,
    const __half* __restrict__ Bs, int ldb, size_t sB,
    float* __restrict__ Cf, __half* __restrict__ Ch, int ldc, size_t sC,
    const float* __restrict__ bias, int bias_mode, int sBias,
    const float* __restrict__ resid, size_t sR,
    int K) {
    extern __shared__ char smem[];
    const uint32_t sb = smem_u32(smem);
    const int tid = threadIdx.x;
    const int wid = tid >> 5, lane = tid & 31;
    const int wm = wid & 1, wn = wid >> 1;
    const int bz = blockIdx.z;
    const int m0 = blockIdx.y * 128, n0 = blockIdx.x * 128;

    const __half* gA = A  + (size_t)bz * sA + (size_t)m0 * lda;
    const __half* gB = Bs + (size_t)bz * sB + (size_t)n0 * ldb;

    float acc[4][8][4] = {};
    const int nt = K >> 5;
#pragma unroll
    for (int s = 0; s < NSTG - 1; ++s) {
        if (s < nt) {
            uint32_t st = sb + s * STAGE;
            ld_tile_async128(gA + (s << 5), lda, st,        tid);
            ld_tile_async128(gB + (s << 5), ldb, st + T_SZ, tid);
        }
        CP_COMMIT();
    }

    const int a_m  = wm * 64 + (lane & 15);
    const int a_k  = (lane >> 4) * 8;
    const int b_nr = wn * 64 + (lane & 7) + ((lane >> 4) << 3);
    const int b_k  = ((lane >> 3) & 1) * 8;

    for (int kt = 0; kt < nt; ++kt) {
        const int pre = kt + NSTG - 1;
        if (pre < nt) {
            uint32_t st = sb + (pre & (NSTG - 1)) * STAGE;
            ld_tile_async128(gA + (pre << 5), lda, st,        tid);
            ld_tile_async128(gB + (pre << 5), ldb, st + T_SZ, tid);
        }
        CP_COMMIT();
        const int rem = nt - 1 - kt;
        if (rem >= NSTG - 2) { CP_WAIT2(); }
        else if (rem == 1)   { CP_WAIT1(); }
        else                 { CP_WAIT0(); }
        __syncthreads();

        const uint32_t st = sb + (kt & (NSTG - 1)) * STAGE;
#pragma unroll
        for (int ks = 0; ks < 2; ++ks) {
            const int kk = ks * 16;
            uint32_t ah[4][4], bb[4][4];
#pragma unroll
            for (int mi = 0; mi < 4; ++mi)
                ldsm_x4(ah[mi], st + (a_m + mi * 16) * (LDS_ * 2) + (kk + a_k) * 2);
#pragma unroll
            for (int nj = 0; nj < 4; ++nj)
                ldsm_x4(bb[nj], st + T_SZ + (b_nr + nj * 16) * (LDS_ * 2) + (kk + b_k) * 2);
#pragma unroll
            for (int mi = 0; mi < 4; ++mi)
#pragma unroll
                for (int nj = 0; nj < 4; ++nj) {
                    mma16816(acc[mi][2 * nj],     ah[mi], bb[nj][0], bb[nj][1]);
                    mma16816(acc[mi][2 * nj + 1], ah[mi], bb[nj][2], bb[nj][3]);
                }
        }
        __syncthreads();
    }

    const int r_in = lane >> 2;
    const int c_in = (lane & 3) * 2;
    const float* bp = bias ? bias + bz * sBias : nullptr;
#pragma unroll
    for (int mi = 0; mi < 4; ++mi) {
        int row0 = m0 + wm * 64 + mi * 16 + r_in;
        int row1 = row0 + 8;
        float rb0 = 0.f, rb1 = 0.f;
        if (bias_mode == 1) { rb0 = bp[row0]; rb1 = bp[row1]; }
#pragma unroll
        for (int ni = 0; ni < 8; ++ni) {
            int col = n0 + wn * 64 + ni * 8 + c_in;
            float cb0 = 0.f, cb1 = 0.f;
            if (bias_mode == 2) { cb0 = bp[col]; cb1 = bp[col + 1]; }
            float v00 = acc[mi][ni][0] + rb0 + cb0;
            float v01 = acc[mi][ni][1] + rb0 + cb1;
            float v10 = acc[mi][ni][2] + rb1 + cb0;
            float v11 = acc[mi][ni][3] + rb1 + cb1;
            if (Cf) {
                float* Cb = Cf + (size_t)bz * sC;
                if (resid) {
                    const float* Rb = resid + (size_t)bz * sR;
                    float2 r0 = *(const float2*)(Rb + (size_t)row0 * ldc + col);
                    float2 r1 = *(const float2*)(Rb + (size_t)row1 * ldc + col);
                    v00 += r0.x; v01 += r0.y; v10 += r1.x; v11 += r1.y;
                }
                *(float2*)(Cb + (size_t)row0 * ldc + col) = make_float2(v00, v01);
                *(float2*)(Cb + (size_t)row1 * ldc + col) = make_float2(v10, v11);
            } else {
                __half* Hb = Ch + (size_t)bz * sC;
                *(__half2*)(Hb + (size_t)row0 * ldc + col) =
                    __halves2half2(__float2half_rn(v00), __float2half_rn(v01));
                *(__half2*)(Hb + (size_t)row1 * ldc + col) =
                    __halves2half2(__float2half_rn(v10), __float2half_rn(v11));
            }
        }
    }
}

// ---- 64x64 tile kernel (for M=N=512 GEMMs; better grid occupancy) --------
#define T64_SZ  (64 * LDS_ * 2)        // 5120 B
#define STAGE64 (2 * T64_SZ)           // 10240 B
#define SMEMB64 (NSTG * STAGE64)       // 40960 B

__device__ __forceinline__ void ld_tile_async64(
    const __half* __restrict__ g, int ldk, uint32_t sbase, int tid) {
#pragma unroll
    for (int i = 0; i < 2; ++i) {
        int idx = tid + i * 128;               // 0..255
        int row = idx >> 2, ch = idx & 3;
        CP_ASYNC16(sbase + row * (LDS_ * 2) + ch * 16,
                   g + (size_t)row * ldk + ch * 8);
    }
}

__global__ __launch_bounds__(128) void hmma_nt64_kernel(
    const __half* __restrict__ A, int lda, size_t sA,
    const __half* __restrict__ Bs, int ldb, size_t sB,
    __half* __restrict__ Ch, int ldc, size_t sC,
    const float* __restrict__ bias, int bias_mode, int sBias,
    int K) {
    extern __shared__ char smem[];
    const uint32_t sb = smem_u32(smem);
    const int tid = threadIdx.x;
    const int wid = tid >> 5, lane = tid & 31;
    const int wm = wid & 1, wn = wid >> 1;    // 2x2 warps, 32x32 each
    const int bz = blockIdx.z;
    const int m0 = blockIdx.y * 64, n0 = blockIdx.x * 64;

    const __half* gA = A  + (size_t)bz * sA + (size_t)m0 * lda;
    const __half* gB = Bs + (size_t)bz * sB + (size_t)n0 * ldb;

    float acc[2][4][4] = {};
    const int nt = K >> 5;
#pragma unroll
    for (int s = 0; s < NSTG - 1; ++s) {
        if (s < nt) {
            uint32_t st = sb + s * STAGE64;
            ld_tile_async64(gA + (s << 5), lda, st,          tid);
            ld_tile_async64(gB + (s << 5), ldb, st + T64_SZ, tid);
        }
        CP_COMMIT();
    }

    const int a_m  = wm * 32 + (lane & 15);
    const int a_k  = (lane >> 4) * 8;
    const int b_nr = wn * 32 + (lane & 7) + ((lane >> 4) << 3);
    const int b_k  = ((lane >> 3) & 1) * 8;

    for (int kt = 0; kt < nt; ++kt) {
        const int pre = kt + NSTG - 1;
        if (pre < nt) {
            uint32_t st = sb + (pre & (NSTG - 1)) * STAGE64;
            ld_tile_async64(gA + (pre << 5), lda, st,          tid);
            ld_tile_async64(gB + (pre << 5), ldb, st + T64_SZ, tid);
        }
        CP_COMMIT();
        const int rem = nt - 1 - kt;
        if (rem >= NSTG - 2) { CP_WAIT2(); }
        else if (rem == 1)   { CP_WAIT1(); }
        else                 { CP_WAIT0(); }
        __syncthreads();

        const uint32_t st = sb + (kt & (NSTG - 1)) * STAGE64;
#pragma unroll
        for (int ks = 0; ks < 2; ++ks) {
            const int kk = ks * 16;
            uint32_t ah[2][4], bb[2][4];
#pragma unroll
            for (int mi = 0; mi < 2; ++mi)
                ldsm_x4(ah[mi], st + (a_m + mi * 16) * (LDS_ * 2) + (kk + a_k) * 2);
#pragma unroll
            for (int nj = 0; nj < 2; ++nj)
                ldsm_x4(bb[nj], st + T64_SZ + (b_nr + nj * 16) * (LDS_ * 2) + (kk + b_k) * 2);
#pragma unroll
            for (int mi = 0; mi < 2; ++mi)
#pragma unroll
                for (int nj = 0; nj < 2; ++nj) {
                    mma16816(acc[mi][2 * nj],     ah[mi], bb[nj][0], bb[nj][1]);
                    mma16816(acc[mi][2 * nj + 1], ah[mi], bb[nj][2], bb[nj][3]);
                }
        }
        __syncthreads();
    }

    const int r_in = lane >> 2;
    const int c_in = (lane & 3) * 2;
    const float* bp = bias ? bias + bz * sBias : nullptr;
    __half* Hb = Ch + (size_t)bz * sC;
#pragma unroll
    for (int mi = 0; mi < 2; ++mi) {
        int row0 = m0 + wm * 32 + mi * 16 + r_in;
        int row1 = row0 + 8;
        float rb0 = 0.f, rb1 = 0.f;
        if (bias_mode == 1) { rb0 = bp[row0]; rb1 = bp[row1]; }
#pragma unroll
        for (int ni = 0; ni < 4; ++ni) {
            int col = n0 + wn * 32 + ni * 8 + c_in;
            float cb0 = 0.f, cb1 = 0.f;
            if (bias_mode == 2) { cb0 = bp[col]; cb1 = bp[col + 1]; }
            float v00 = acc[mi][ni][0] + rb0 + cb0;
            float v01 = acc[mi][ni][1] + rb0 + cb1;
            float v10 = acc[mi][ni][2] + rb1 + cb0;
            float v11 = acc[mi][ni][3] + rb1 + cb1;
            *(__half2*)(Hb + (size_t)row0 * ldc + col) =
                __halves2half2(__float2half_rn(v00), __float2half_rn(v01));
            *(__half2*)(Hb + (size_t)row1 * ldc + col) =
                __halves2half2(__float2half_rn(v10), __float2half_rn(v11));
        }
    }
}

// ---------------------------------------------------------------------------
// Launch sequence
// ---------------------------------------------------------------------------
extern "C" void kernel_launch(void* const* d_in, const int* in_sizes, int n_in,
                              void* d_out, int out_size) {
    const float* x        = (const float*)d_in[0];
    const float* qkv_w    = (const float*)d_in[1];
    const float* qkv_b    = (const float*)d_in[2];
    const float* proj_w   = (const float*)d_in[3];
    const float* proj_b   = (const float*)d_in[4];
    const float* gn_scale = (const float*)d_in[5];
    const float* gn_bias  = (const float*)d_in[6];
    float* out = (float*)d_out;

    cudaFuncSetAttribute(hmma_nt_kernel, cudaFuncAttributeMaxDynamicSharedMemorySize, SMEMB);
    cudaFuncSetAttribute(hmma_nt64_kernel, cudaFuncAttributeMaxDynamicSharedMemorySize, SMEMB64);

    float *biasb, *kf, *fb;
    __half *Wh, *xTh, *xh, *kh, *kxh, *ctxh, *Mh, *Eh, *wqTh, *pwh;
    cudaGetSymbolAddress((void**)&biasb, g_biasb);
    cudaGetSymbolAddress((void**)&kf, g_kf);
    cudaGetSymbolAddress((void**)&fb, g_fb);
    cudaGetSymbolAddress((void**)&Wh, g_Wh);
    cudaGetSymbolAddress((void**)&xTh, g_xTh);
    cudaGetSymbolAddress((void**)&xh, g_xh);
    cudaGetSymbolAddress((void**)&kh, g_kh);
    cudaGetSymbolAddress((void**)&kxh, g_kxh);
    cudaGetSymbolAddress((void**)&ctxh, g_ctxh);
    cudaGetSymbolAddress((void**)&Mh, g_Mh);
    cudaGetSymbolAddress((void**)&Eh, g_Eh);
    cudaGetSymbolAddress((void**)&wqTh, g_wqTh);
    cudaGetSymbolAddress((void**)&pwh, g_pwh);

    // 1) GN stats, weight folding, converts (tconv also emits xh)
    gn_stats_kernel<<<B_ * G_, 256>>>(x);
    prep_w_kernel<<<B_ * O3, 128>>>(qkv_w, qkv_b, gn_scale, gn_bias);
    f2h_kernel<<<(C_ * C_ / 4 + 255) / 256, 256>>>(proj_w, pwh, C_ * C_ / 4);
    tconv_kernel<<<dim3(N_ / 32, C_ / 64, B_), dim3(32, 8)>>>(x, xTh, xh);
    wqt_kernel<<<dim3(C_ / 32, C_ / 32, B_), dim3(32, 8)>>>();
    // 2) k logits (fp32): k[d,n] = Wk . xT + bk
    hmma_nt_kernel<<<dim3(N_ / 128, C_ / 128, B_), 128, SMEMB>>>(
        Wh + (size_t)C_ * C_, C_, (size_t)O3 * C_,
        xTh, C_, (size_t)N_ * C_,
        kf, nullptr, N_, (size_t)C_ * N_,
        biasb + C_, 1, O3, nullptr, 0, C_);
    // 3) softmax over tokens
    softmax_kernel<<<B_ * C_, 256>>>(kf, kh);
    // 4) kx[d,c] = k_sm . x^T   (K=4096) — 64-tile, 512 blocks
    hmma_nt64_kernel<<<dim3(C_ / 64, C_ / 64, B_), 128, SMEMB64>>>(
        kh, N_, (size_t)C_ * N_,
        xh, N_, (size_t)C_ * N_,
        kxh, C_, (size_t)C_ * C_,
        nullptr, 0, 0, N_);
    // 5) ctx[d,e] = kx . Wv^T + bv[e] — 64-tile
    hmma_nt64_kernel<<<dim3(C_ / 64, C_ / 64, B_), 128, SMEMB64>>>(
        kxh, C_, (size_t)C_ * C_,
        Wh + (size_t)2 * C_ * C_, C_, (size_t)O3 * C_,
        ctxh, C_, (size_t)C_ * C_,
        biasb + 2 * C_, 2, O3, C_);
    // 6) M[o,d] = proj_w . ctx^T — 64-tile
    hmma_nt64_kernel<<<dim3(C_ / 64, C_ / 64, B_), 128, SMEMB64>>>(
        pwh, C_, 0,
        ctxh, C_, (size_t)C_ * C_,
        Mh, C_, (size_t)C_ * C_,
        nullptr, 0, 0, C_);
    // 7) E[o,c] = M . WqT^T  (= M @ Wq) — 64-tile
    hmma_nt64_kernel<<<dim3(C_ / 64, C_ / 64, B_), 128, SMEMB64>>>(
        Mh, C_, (size_t)C_ * C_,
        wqTh, C_, (size_t)C_ * C_,
        Eh, C_, (size_t)C_ * C_,
        nullptr, 0, 0, C_);
    // 8) fb = proj_b + M @ bq
    fb_kernel<<<B_ * C_ / 8, 256>>>(proj_b);
    // 9) out[o,n] = E . xT^T + fb[o] + x
    hmma_nt_kernel<<<dim3(N_ / 128, C_ / 128, B_), 128, SMEMB>>>(
        Eh, C_, (size_t)C_ * C_,
        xTh, C_, (size_t)N_ * C_,
        out, nullptr, N_, (size_t)C_ * N_,
        fb, 1, C_, x, (size_t)C_ * N_, C_);
}

// round 8
// speedup vs baseline: 6.3228x; 1.1425x over previous
#include <cuda_runtime.h>
#include <cuda_fp16.h>
#include <cstdint>
#include <math.h>

// Problem constants
#define B_   8
#define C_   512
#define N_   4096
#define G_   8
#define CPG  64
#define O3   1536
#define EPSV 1e-6f
#define QSCALE 0.04419417382415922f   // 512^-0.5

// ---------------------------------------------------------------------------
// PTX helpers
// ---------------------------------------------------------------------------
__device__ __forceinline__ uint32_t smem_u32(const void* p) {
    uint32_t a;
    asm("{ .reg .u64 t; cvta.to.shared.u64 t, %1; cvt.u32.u64 %0, t; }" : "=r"(a) : "l"(p));
    return a;
}
__device__ __forceinline__ void ldsm_x4(uint32_t (&r)[4], uint32_t addr) {
    asm volatile("ldmatrix.sync.aligned.m8n8.x4.shared.b16 {%0,%1,%2,%3}, [%4];"
        : "=r"(r[0]), "=r"(r[1]), "=r"(r[2]), "=r"(r[3]) : "r"(addr));
}
__device__ __forceinline__ void mma16816(float (&d)[4], const uint32_t (&a)[4],
                                         uint32_t b0, uint32_t b1) {
    asm volatile(
        "mma.sync.aligned.m16n8k16.row.col.f32.f16.f16.f32 "
        "{%0,%1,%2,%3}, {%4,%5,%6,%7}, {%8,%9}, {%0,%1,%2,%3};"
        : "+f"(d[0]), "+f"(d[1]), "+f"(d[2]), "+f"(d[3])
        : "r"(a[0]), "r"(a[1]), "r"(a[2]), "r"(a[3]), "r"(b0), "r"(b1));
}
#define CP_ASYNC16(dst, src) \
    asm volatile("cp.async.cg.shared.global [%0], [%1], 16;" :: "r"(dst), "l"(src))
#define CP_COMMIT() asm volatile("cp.async.commit_group;" ::: "memory")
#define CP_WAIT0()  asm volatile("cp.async.wait_group 0;" ::: "memory")
#define CP_WAIT1()  asm volatile("cp.async.wait_group 1;" ::: "memory")
#define CP_WAIT2()  asm volatile("cp.async.wait_group 2;" ::: "memory")

// ---------------------------------------------------------------------------
// Scratch
// ---------------------------------------------------------------------------
__device__ __half g_Wh[(size_t)B_ * O3 * C_];
__device__ float  g_biasb[B_ * O3];
__device__ float  g_mean[B_ * G_], g_rstd[B_ * G_];
__device__ float  g_ssum[B_ * G_], g_ssq[B_ * G_];
__device__ __half g_xTh[(size_t)B_ * N_ * C_];        // x token-major fp16
__device__ __half g_xh [(size_t)B_ * C_ * N_];        // x channel-major fp16
__device__ __half g_khl[(size_t)B_ * C_ * N_];        // k logits fp16
__device__ __half g_kh[(size_t)B_ * C_ * N_];         // softmaxed k fp16
__device__ __half g_kxh[(size_t)B_ * C_ * C_];        // k_sm @ x^T
__device__ __half g_ctxh[(size_t)B_ * C_ * C_];
__device__ __half g_Mh[(size_t)B_ * C_ * C_];
__device__ __half g_Eh[(size_t)B_ * C_ * C_];         // M @ Wq
__device__ __half g_wqTh[(size_t)B_ * C_ * C_];       // Wq transposed [c,o]
__device__ __half g_pwh[C_ * C_];
__device__ float  g_fb[B_ * C_];                      // final fused bias

// ---------------------------------------------------------------------------
// Reductions
// ---------------------------------------------------------------------------
__device__ __forceinline__ float warp_sum(float v) {
#pragma unroll
    for (int o = 16; o > 0; o >>= 1) v += __shfl_xor_sync(0xffffffffu, v, o);
    return v;
}
__device__ __forceinline__ float warp_max(float v) {
#pragma unroll
    for (int o = 16; o > 0; o >>= 1) v = fmaxf(v, __shfl_xor_sync(0xffffffffu, v, o));
    return v;
}
__device__ __forceinline__ float block_sum(float v, float* sh) {
    int tid = threadIdx.x, nw = blockDim.x >> 5;
    __syncthreads();
    v = warp_sum(v);
    if ((tid & 31) == 0) sh[tid >> 5] = v;
    __syncthreads();
    if (tid < 32) {
        float w = (tid < nw) ? sh[tid] : 0.f;
        w = warp_sum(w);
        if (tid == 0) sh[0] = w;
    }
    __syncthreads();
    return sh[0];
}
__device__ __forceinline__ float block_max(float v, float* sh) {
    int tid = threadIdx.x, nw = blockDim.x >> 5;
    __syncthreads();
    v = warp_max(v);
    if ((tid & 31) == 0) sh[tid >> 5] = v;
    __syncthreads();
    if (tid < 32) {
        float w = (tid < nw) ? sh[tid] : -3.402823466e38f;
        w = warp_max(w);
        if (tid == 0) sh[0] = w;
    }
    __syncthreads();
    return sh[0];
}

// ---------------------------------------------------------------------------
// Stats init / finalize
// ---------------------------------------------------------------------------
__global__ void init_stats_kernel() {
    int i = threadIdx.x;
    if (i < B_ * G_) { g_ssum[i] = 0.f; g_ssq[i] = 0.f; }
}
__global__ void stats_fin_kernel() {
    int i = threadIdx.x;
    if (i < B_ * G_) {
        const float inv = 1.f / (float)(CPG * N_);
        float m = g_ssum[i] * inv;
        g_mean[i] = m;
        g_rstd[i] = rsqrtf(g_ssq[i] * inv - m * m + EPSV);
    }
}

// ---------------------------------------------------------------------------
// Fused: x [C,N] fp32 -> xh (same layout fp16) + xT [N,C] fp16 + GN stats.
// grid (N/32, G, B), block 256. Each block: 64 channels (one group) x 32 tokens.
// ---------------------------------------------------------------------------
__global__ __launch_bounds__(256) void tconv_gn_kernel(
    const float* __restrict__ in, __half* __restrict__ outT,
    __half* __restrict__ outCh) {
    __shared__ float t[64][33];
    __shared__ float sh[32];
    int b = blockIdx.z, g = blockIdx.y;
    int n0 = blockIdx.x * 32, c0 = g * 64;
    const float* ip = in + (size_t)b * C_ * N_;
    __half* chp = outCh + (size_t)b * C_ * N_;
    int tid = threadIdx.x;
    int q = tid & 7, r0 = tid >> 3;          // 8 quads x 32 rows per pass
    float s = 0.f, ss = 0.f;
#pragma unroll
    for (int pass = 0; pass < 2; ++pass) {
        int c = r0 + pass * 32;
        float4 v = *(const float4*)(ip + (size_t)(c0 + c) * N_ + n0 + q * 4);
        s += v.x + v.y + v.z + v.w;
        ss = fmaf(v.x, v.x, fmaf(v.y, v.y, fmaf(v.z, v.z, fmaf(v.w, v.w, ss))));
        __half2* hp = (__half2*)(chp + (size_t)(c0 + c) * N_ + n0 + q * 4);
        hp[0] = __halves2half2(__float2half_rn(v.x), __float2half_rn(v.y));
        hp[1] = __halves2half2(__float2half_rn(v.z), __float2half_rn(v.w));
        t[c][q * 4 + 0] = v.x; t[c][q * 4 + 1] = v.y;
        t[c][q * 4 + 2] = v.z; t[c][q * 4 + 3] = v.w;
    }
    // stats (block_sum's internal barriers also make t[] visible)
    float bs  = block_sum(s, sh);
    float bss = block_sum(ss, sh);
    if (tid == 0) {
        atomicAdd(&g_ssum[b * G_ + g], bs);
        atomicAdd(&g_ssq [b * G_ + g], bss);
    }
    // transpose: lanes sweep c (coalesced half2 writes), rows sweep n
    __half* op = outT + (size_t)b * N_ * C_;
    int c2 = tid & 31;                        // half2 column group: c = 2*c2
    int nr = tid >> 5;                        // 8 n-rows per pass
#pragma unroll
    for (int pass = 0; pass < 4; ++pass) {
        int n = nr + pass * 8;
        int c = c2 * 2;
        __half2 hv = __halves2half2(__float2half_rn(t[c][n]),
                                    __float2half_rn(t[c + 1][n]));
        *(__half2*)(op + (size_t)(n0 + n) * C_ + c0 + c) = hv;
    }
}

// ---------------------------------------------------------------------------
// Fold GN (+q scale) into qkv weights -> fp16; fold means into bias (fp32)
// ---------------------------------------------------------------------------
__global__ __launch_bounds__(128) void prep_w_kernel(
    const float* __restrict__ qkv_w, const float* __restrict__ qkv_b,
    const float* __restrict__ gn_scale, const float* __restrict__ gn_bias) {
    int bo = blockIdx.x;
    int b = bo / O3, o = bo % O3;
    float qs = (o < C_) ? QSCALE : 1.f;
    const float* wrow = qkv_w + (size_t)o * C_;
    __half* wh = g_Wh + (size_t)bo * C_;
    float acc = 0.f;
    for (int c = threadIdx.x; c < C_; c += 128) {
        int g = c >> 6;
        float rstd = g_rstd[b * G_ + g];
        float mean = g_mean[b * G_ + g];
        float a = rstd * gn_scale[c];
        float d = gn_bias[c] - mean * a;
        float w = wrow[c];
        wh[c] = __float2half_rn(w * a * qs);
        acc = fmaf(w, d, acc);
    }
    __shared__ float sh[32];
    acc = block_sum(acc, sh);
    if (threadIdx.x == 0) g_biasb[bo] = qs * (qkv_b[o] + acc);
}

// ---------------------------------------------------------------------------
// fp32 -> fp16 convert (proj_w)
// ---------------------------------------------------------------------------
__global__ __launch_bounds__(256) void f2h_kernel(
    const float* __restrict__ in, __half* __restrict__ out, size_t n4) {
    size_t i = (size_t)blockIdx.x * 256 + threadIdx.x;
    if (i >= n4) return;
    float4 v = ((const float4*)in)[i];
    __half2* o = (__half2*)(out + i * 4);
    o[0] = __halves2half2(__float2half_rn(v.x), __float2half_rn(v.y));
    o[1] = __halves2half2(__float2half_rn(v.z), __float2half_rn(v.w));
}

// ---------------------------------------------------------------------------
// Transpose q-slab of folded weights: Wq [o,c] -> wqT [c,o]  (fp16, per batch)
// ---------------------------------------------------------------------------
__global__ __launch_bounds__(256) void wqt_kernel() {
    __shared__ __half t[32][33];
    int b = blockIdx.z;
    const __half* W = g_Wh + (size_t)b * O3 * C_;
    __half* outp = g_wqTh + (size_t)b * C_ * C_;
    int c0 = blockIdx.x * 32, o0 = blockIdx.y * 32;
    int tx = threadIdx.x, ty = threadIdx.y;
    for (int j = ty; j < 32; j += 8)
        t[j][tx] = W[(size_t)(o0 + j) * C_ + c0 + tx];
    __syncthreads();
    for (int j = ty; j < 32; j += 8)
        outp[(size_t)(c0 + j) * C_ + o0 + tx] = t[tx][j];
}

// ---------------------------------------------------------------------------
// Row softmax: fp16 logits -> fp16 probabilities (fp32 math inside)
// ---------------------------------------------------------------------------
__global__ __launch_bounds__(256) void softmax_kernel(
    const __half* __restrict__ kl, __half* __restrict__ kh) {
    int row = blockIdx.x;
    const __half2* p = (const __half2*)(kl + (size_t)row * N_);
    __half2* o = (__half2*)(kh + (size_t)row * N_);
    const int tid = threadIdx.x;
    float2 v[8];
    float mx = -3.402823466e38f;
#pragma unroll
    for (int i = 0; i < 8; i++) {
        v[i] = __half22float2(p[tid + i * 256]);
        mx = fmaxf(mx, fmaxf(v[i].x, v[i].y));
    }
    __shared__ float sh[32];
    mx = block_max(mx, sh);
    float s = 0.f;
#pragma unroll
    for (int i = 0; i < 8; i++) {
        v[i].x = __expf(v[i].x - mx); v[i].y = __expf(v[i].y - mx);
        s += v[i].x + v[i].y;
    }
    s = block_sum(s, sh);
    float inv = 1.f / s;
#pragma unroll
    for (int i = 0; i < 8; i++) {
        o[tid + i * 256] = __halves2half2(__float2half_rn(v[i].x * inv),
                                          __float2half_rn(v[i].y * inv));
    }
}

// ---------------------------------------------------------------------------
// fb[b,o] = proj_b[o] + sum_d M[b,o,d] * bq_b[b,d]
// ---------------------------------------------------------------------------
__global__ __launch_bounds__(256) void fb_kernel(const float* __restrict__ proj_b) {
    int r = blockIdx.x * 8 + (threadIdx.x >> 5);
    int b = r / C_, o = r % C_;
    const __half* Mrow = g_Mh + ((size_t)b * C_ + o) * C_;
    const float* bq = g_biasb + b * O3;
    int lane = threadIdx.x & 31;
    float s = 0.f;
    for (int d = lane; d < C_; d += 32)
        s += __half2float(Mrow[d]) * bq[d];
    s = warp_sum(s);
    if (lane == 0) g_fb[r] = s + proj_b[o];
}

// ---------------------------------------------------------------------------
// Shared GEMM plumbing
// ---------------------------------------------------------------------------
#define LDS_   40
#define NSTG   4

// ---- 128x128 tile kernel -------------------------------------------------
#define T_SZ   (128 * LDS_ * 2)        // 10240 B
#define STAGE  (2 * T_SZ)
#define SMEMB  (NSTG * STAGE)          // 81920 B

__device__ __forceinline__ void ld_tile_async128(
    const __half* __restrict__ g, int ldk, uint32_t sbase, int tid) {
#pragma unroll
    for (int i = 0; i < 4; ++i) {
        int idx = tid + i * 128;
        int row = idx >> 2, ch = idx & 3;
        CP_ASYNC16(sbase + row * (LDS_ * 2) + ch * 16,
                   g + (size_t)row * ldk + ch * 8);
    }
}

__global__ __launch_bounds__(128) void hmma_nt_kernel(
    const __half* __restrict__ A, int lda, size_t sA,
    const __half* __restrict__ Bs, int ldb, size_t sB,
    float* __restrict__ Cf, __half* __restrict__ Ch, int ldc, size_t sC,
    const float* __restrict__ bias, int bias_mode, int sBias,
    const float* __restrict__ resid, size_t sR,
    int K) {
    extern __shared__ char smem[];
    const uint32_t sb = smem_u32(smem);
    const int tid = threadIdx.x;
    const int wid = tid >> 5, lane = tid & 31;
    const int wm = wid & 1, wn = wid >> 1;
    const int bz = blockIdx.z;
    const int m0 = blockIdx.y * 128, n0 = blockIdx.x * 128;

    const __half* gA = A  + (size_t)bz * sA + (size_t)m0 * lda;
    const __half* gB = Bs + (size_t)bz * sB + (size_t)n0 * ldb;

    float acc[4][8][4] = {};
    const int nt = K >> 5;
#pragma unroll
    for (int s = 0; s < NSTG - 1; ++s) {
        if (s < nt) {
            uint32_t st = sb + s * STAGE;
            ld_tile_async128(gA + (s << 5), lda, st,        tid);
            ld_tile_async128(gB + (s << 5), ldb, st + T_SZ, tid);
        }
        CP_COMMIT();
    }

    const int a_m  = wm * 64 + (lane & 15);
    const int a_k  = (lane >> 4) * 8;
    const int b_nr = wn * 64 + (lane & 7) + ((lane >> 4) << 3);
    const int b_k  = ((lane >> 3) & 1) * 8;

    for (int kt = 0; kt < nt; ++kt) {
        const int pre = kt + NSTG - 1;
        if (pre < nt) {
            uint32_t st = sb + (pre & (NSTG - 1)) * STAGE;
            ld_tile_async128(gA + (pre << 5), lda, st,        tid);
            ld_tile_async128(gB + (pre << 5), ldb, st + T_SZ, tid);
        }
        CP_COMMIT();
        const int rem = nt - 1 - kt;
        if (rem >= NSTG - 2) { CP_WAIT2(); }
        else if (rem == 1)   { CP_WAIT1(); }
        else                 { CP_WAIT0(); }
        __syncthreads();

        const uint32_t st = sb + (kt & (NSTG - 1)) * STAGE;
#pragma unroll
        for (int ks = 0; ks < 2; ++ks) {
            const int kk = ks * 16;
            uint32_t ah[4][4], bb[4][4];
#pragma unroll
            for (int mi = 0; mi < 4; ++mi)
                ldsm_x4(ah[mi], st + (a_m + mi * 16) * (LDS_ * 2) + (kk + a_k) * 2);
#pragma unroll
            for (int nj = 0; nj < 4; ++nj)
                ldsm_x4(bb[nj], st + T_SZ + (b_nr + nj * 16) * (LDS_ * 2) + (kk + b_k) * 2);
#pragma unroll
            for (int mi = 0; mi < 4; ++mi)
#pragma unroll
                for (int nj = 0; nj < 4; ++nj) {
                    mma16816(acc[mi][2 * nj],     ah[mi], bb[nj][0], bb[nj][1]);
                    mma16816(acc[mi][2 * nj + 1], ah[mi], bb[nj][2], bb[nj][3]);
                }
        }
        __syncthreads();
    }

    const int r_in = lane >> 2;
    const int c_in = (lane & 3) * 2;
    const float* bp = bias ? bias + bz * sBias : nullptr;
#pragma unroll
    for (int mi = 0; mi < 4; ++mi) {
        int row0 = m0 + wm * 64 + mi * 16 + r_in;
        int row1 = row0 + 8;
        float rb0 = 0.f, rb1 = 0.f;
        if (bias_mode == 1) { rb0 = bp[row0]; rb1 = bp[row1]; }
#pragma unroll
        for (int ni = 0; ni < 8; ++ni) {
            int col = n0 + wn * 64 + ni * 8 + c_in;
            float cb0 = 0.f, cb1 = 0.f;
            if (bias_mode == 2) { cb0 = bp[col]; cb1 = bp[col + 1]; }
            float v00 = acc[mi][ni][0] + rb0 + cb0;
            float v01 = acc[mi][ni][1] + rb0 + cb1;
            float v10 = acc[mi][ni][2] + rb1 + cb0;
            float v11 = acc[mi][ni][3] + rb1 + cb1;
            if (Cf) {
                float* Cb = Cf + (size_t)bz * sC;
                if (resid) {
                    const float* Rb = resid + (size_t)bz * sR;
                    float2 r0 = *(const float2*)(Rb + (size_t)row0 * ldc + col);
                    float2 r1 = *(const float2*)(Rb + (size_t)row1 * ldc + col);
                    v00 += r0.x; v01 += r0.y; v10 += r1.x; v11 += r1.y;
                }
                *(float2*)(Cb + (size_t)row0 * ldc + col) = make_float2(v00, v01);
                *(float2*)(Cb + (size_t)row1 * ldc + col) = make_float2(v10, v11);
            } else {
                __half* Hb = Ch + (size_t)bz * sC;
                *(__half2*)(Hb + (size_t)row0 * ldc + col) =
                    __halves2half2(__float2half_rn(v00), __float2half_rn(v01));
                *(__half2*)(Hb + (size_t)row1 * ldc + col) =
                    __halves2half2(__float2half_rn(v10), __float2half_rn(v11));
            }
        }
    }
}

// ---- 64x64 tile kernel (for M=N=512 GEMMs) -------------------------------
#define T64_SZ  (64 * LDS_ * 2)        // 5120 B
#define STAGE64 (2 * T64_SZ)           // 10240 B
#define SMEMB64 (NSTG * STAGE64)       // 40960 B

__device__ __forceinline__ void ld_tile_async64(
    const __half* __restrict__ g, int ldk, uint32_t sbase, int tid) {
#pragma unroll
    for (int i = 0; i < 2; ++i) {
        int idx = tid + i * 128;
        int row = idx >> 2, ch = idx & 3;
        CP_ASYNC16(sbase + row * (LDS_ * 2) + ch * 16,
                   g + (size_t)row * ldk + ch * 8);
    }
}

__global__ __launch_bounds__(128) void hmma_nt64_kernel(
    const __half* __restrict__ A, int lda, size_t sA,
    const __half* __restrict__ Bs, int ldb, size_t sB,
    __half* __restrict__ Ch, int ldc, size_t sC,
    const float* __restrict__ bias, int bias_mode, int sBias,
    int K) {
    extern __shared__ char smem[];
    const uint32_t sb = smem_u32(smem);
    const int tid = threadIdx.x;
    const int wid = tid >> 5, lane = tid & 31;
    const int wm = wid & 1, wn = wid >> 1;
    const int bz = blockIdx.z;
    const int m0 = blockIdx.y * 64, n0 = blockIdx.x * 64;

    const __half* gA = A  + (size_t)bz * sA + (size_t)m0 * lda;
    const __half* gB = Bs + (size_t)bz * sB + (size_t)n0 * ldb;

    float acc[2][4][4] = {};
    const int nt = K >> 5;
#pragma unroll
    for (int s = 0; s < NSTG - 1; ++s) {
        if (s < nt) {
            uint32_t st = sb + s * STAGE64;
            ld_tile_async64(gA + (s << 5), lda, st,          tid);
            ld_tile_async64(gB + (s << 5), ldb, st + T64_SZ, tid);
        }
        CP_COMMIT();
    }

    const int a_m  = wm * 32 + (lane & 15);
    const int a_k  = (lane >> 4) * 8;
    const int b_nr = wn * 32 + (lane & 7) + ((lane >> 4) << 3);
    const int b_k  = ((lane >> 3) & 1) * 8;

    for (int kt = 0; kt < nt; ++kt) {
        const int pre = kt + NSTG - 1;
        if (pre < nt) {
            uint32_t st = sb + (pre & (NSTG - 1)) * STAGE64;
            ld_tile_async64(gA + (pre << 5), lda, st,          tid);
            ld_tile_async64(gB + (pre << 5), ldb, st + T64_SZ, tid);
        }
        CP_COMMIT();
        const int rem = nt - 1 - kt;
        if (rem >= NSTG - 2) { CP_WAIT2(); }
        else if (rem == 1)   { CP_WAIT1(); }
        else                 { CP_WAIT0(); }
        __syncthreads();

        const uint32_t st = sb + (kt & (NSTG - 1)) * STAGE64;
#pragma unroll
        for (int ks = 0; ks < 2; ++ks) {
            const int kk = ks * 16;
            uint32_t ah[2][4], bb[2][4];
#pragma unroll
            for (int mi = 0; mi < 2; ++mi)
                ldsm_x4(ah[mi], st + (a_m + mi * 16) * (LDS_ * 2) + (kk + a_k) * 2);
#pragma unroll
            for (int nj = 0; nj < 2; ++nj)
                ldsm_x4(bb[nj], st + T64_SZ + (b_nr + nj * 16) * (LDS_ * 2) + (kk + b_k) * 2);
#pragma unroll
            for (int mi = 0; mi < 2; ++mi)
#pragma unroll
                for (int nj = 0; nj < 2; ++nj) {
                    mma16816(acc[mi][2 * nj],     ah[mi], bb[nj][0], bb[nj][1]);
                    mma16816(acc[mi][2 * nj + 1], ah[mi], bb[nj][2], bb[nj][3]);
                }
        }
        __syncthreads();
    }

    const int r_in = lane >> 2;
    const int c_in = (lane & 3) * 2;
    const float* bp = bias ? bias + bz * sBias : nullptr;
    __half* Hb = Ch + (size_t)bz * sC;
#pragma unroll
    for (int mi = 0; mi < 2; ++mi) {
        int row0 = m0 + wm * 32 + mi * 16 + r_in;
        int row1 = row0 + 8;
        float rb0 = 0.f, rb1 = 0.f;
        if (bias_mode == 1) { rb0 = bp[row0]; rb1 = bp[row1]; }
#pragma unroll
        for (int ni = 0; ni < 4; ++ni) {
            int col = n0 + wn * 32 + ni * 8 + c_in;
            float cb0 = 0.f, cb1 = 0.f;
            if (bias_mode == 2) { cb0 = bp[col]; cb1 = bp[col + 1]; }
            float v00 = acc[mi][ni][0] + rb0 + cb0;
            float v01 = acc[mi][ni][1] + rb0 + cb1;
            float v10 = acc[mi][ni][2] + rb1 + cb0;
            float v11 = acc[mi][ni][3] + rb1 + cb1;
            *(__half2*)(Hb + (size_t)row0 * ldc + col) =
                __halves2half2(__float2half_rn(v00), __float2half_rn(v01));
            *(__half2*)(Hb + (size_t)row1 * ldc + col) =
                __halves2half2(__float2half_rn(v10), __float2half_rn(v11));
        }
    }
}

// ---------------------------------------------------------------------------
// Launch sequence
// ---------------------------------------------------------------------------
extern "C" void kernel_launch(void* const* d_in, const int* in_sizes, int n_in,
                              void* d_out, int out_size) {
    const float* x        = (const float*)d_in[0];
    const float* qkv_w    = (const float*)d_in[1];
    const float* qkv_b    = (const float*)d_in[2];
    const float* proj_w   = (const float*)d_in[3];
    const float* proj_b   = (const float*)d_in[4];
    const float* gn_scale = (const float*)d_in[5];
    const float* gn_bias  = (const float*)d_in[6];
    float* out = (float*)d_out;

    cudaFuncSetAttribute(hmma_nt_kernel, cudaFuncAttributeMaxDynamicSharedMemorySize, SMEMB);
    cudaFuncSetAttribute(hmma_nt64_kernel, cudaFuncAttributeMaxDynamicSharedMemorySize, SMEMB64);

    float *biasb, *fb;
    __half *Wh, *xTh, *xh, *khl, *kh, *kxh, *ctxh, *Mh, *Eh, *wqTh, *pwh;
    cudaGetSymbolAddress((void**)&biasb, g_biasb);
    cudaGetSymbolAddress((void**)&fb, g_fb);
    cudaGetSymbolAddress((void**)&Wh, g_Wh);
    cudaGetSymbolAddress((void**)&xTh, g_xTh);
    cudaGetSymbolAddress((void**)&xh, g_xh);
    cudaGetSymbolAddress((void**)&khl, g_khl);
    cudaGetSymbolAddress((void**)&kh, g_kh);
    cudaGetSymbolAddress((void**)&kxh, g_kxh);
    cudaGetSymbolAddress((void**)&ctxh, g_ctxh);
    cudaGetSymbolAddress((void**)&Mh, g_Mh);
    cudaGetSymbolAddress((void**)&Eh, g_Eh);
    cudaGetSymbolAddress((void**)&wqTh, g_wqTh);
    cudaGetSymbolAddress((void**)&pwh, g_pwh);

    // 1) fused convert/transpose/stats, then finalize + weight folding
    init_stats_kernel<<<1, 64>>>();
    tconv_gn_kernel<<<dim3(N_ / 32, G_, B_), 256>>>(x, xTh, xh);
    stats_fin_kernel<<<1, 64>>>();
    prep_w_kernel<<<B_ * O3, 128>>>(qkv_w, qkv_b, gn_scale, gn_bias);
    f2h_kernel<<<(C_ * C_ / 4 + 255) / 256, 256>>>(proj_w, pwh, C_ * C_ / 4);
    wqt_kernel<<<dim3(C_ / 32, C_ / 32, B_), dim3(32, 8)>>>();
    // 2) k logits (fp16 out): k[d,n] = Wk . xT + bk
    hmma_nt_kernel<<<dim3(N_ / 128, C_ / 128, B_), 128, SMEMB>>>(
        Wh + (size_t)C_ * C_, C_, (size_t)O3 * C_,
        xTh, C_, (size_t)N_ * C_,
        nullptr, khl, N_, (size_t)C_ * N_,
        biasb + C_, 1, O3, nullptr, 0, C_);
    // 3) softmax over tokens (fp16 in/out)
    softmax_kernel<<<B_ * C_, 256>>>(khl, kh);
    // 4) kx[d,c] = k_sm . x^T   (K=4096)
    hmma_nt64_kernel<<<dim3(C_ / 64, C_ / 64, B_), 128, SMEMB64>>>(
        kh, N_, (size_t)C_ * N_,
        xh, N_, (size_t)C_ * N_,
        kxh, C_, (size_t)C_ * C_,
        nullptr, 0, 0, N_);
    // 5) ctx[d,e] = kx . Wv^T + bv[e]
    hmma_nt64_kernel<<<dim3(C_ / 64, C_ / 64, B_), 128, SMEMB64>>>(
        kxh, C_, (size_t)C_ * C_,
        Wh + (size_t)2 * C_ * C_, C_, (size_t)O3 * C_,
        ctxh, C_, (size_t)C_ * C_,
        biasb + 2 * C_, 2, O3, C_);
    // 6) M[o,d] = proj_w . ctx^T
    hmma_nt64_kernel<<<dim3(C_ / 64, C_ / 64, B_), 128, SMEMB64>>>(
        pwh, C_, 0,
        ctxh, C_, (size_t)C_ * C_,
        Mh, C_, (size_t)C_ * C_,
        nullptr, 0, 0, C_);
    // 7) E[o,c] = M . WqT^T  (= M @ Wq)
    hmma_nt64_kernel<<<dim3(C_ / 64, C_ / 64, B_), 128, SMEMB64>>>(
        Mh, C_, (size_t)C_ * C_,
        wqTh, C_, (size_t)C_ * C_,
        Eh, C_, (size_t)C_ * C_,
        nullptr, 0, 0, C_);
    // 8) fb = proj_b + M @ bq
    fb_kernel<<<B_ * C_ / 8, 256>>>(proj_b);
    // 9) out[o,n] = E . xT^T + fb[o] + x
    hmma_nt_kernel<<<dim3(N_ / 128, C_ / 128, B_), 128, SMEMB>>>(
        Eh, C_, (size_t)C_ * C_,
        xTh, C_, (size_t)N_ * C_,
        out, nullptr, N_, (size_t)C_ * N_,
        fb, 1, C_, x, (size_t)C_ * N_, C_);
}